// round 12
// baseline (speedup 1.0000x reference)
#include <cuda_runtime.h>
#include <cuda_bf16.h>
#include <cstdint>

#define N_UTT 16384
#define DIM   256
#define WHALF 64
#define WIN   128
#define G     16
#define NW    143            // WIN + G - 1
#define NPAD  144

// Scratch: [0]=Q=x@W_att, [1]=T1p=x@Wc1, [2]=T1s=x@Wc2, [3]=T2=x@Wc3
__device__ float g_scratch[4ULL * N_UTT * DIM];
__device__ __align__(16) unsigned short g_xhi[N_UTT * DIM];
__device__ __align__(16) unsigned short g_xlo[N_UTT * DIM];
__device__ __align__(16) unsigned short g_wthi[4 * DIM * DIM];
__device__ __align__(16) unsigned short g_wtlo[4 * DIM * DIM];

__device__ __forceinline__ uint32_t smem_to_u32(const void* p) {
    uint32_t a;
    asm("{ .reg .u64 t; cvta.to.shared.u64 t, %1; cvt.u32.u64 %0, t; }" : "=r"(a) : "l"(p));
    return a;
}
__device__ __forceinline__ void ldsm_x4(uint32_t* r, uint32_t addr) {
    asm volatile("ldmatrix.sync.aligned.m8n8.x4.shared.b16 {%0,%1,%2,%3}, [%4];"
                 : "=r"(r[0]), "=r"(r[1]), "=r"(r[2]), "=r"(r[3]) : "r"(addr));
}
__device__ __forceinline__ void mma16816(float* c, const uint32_t* a, const uint32_t* b) {
    asm volatile(
        "mma.sync.aligned.m16n8k16.row.col.f32.bf16.bf16.f32 "
        "{%0,%1,%2,%3}, {%4,%5,%6,%7}, {%8,%9}, {%0,%1,%2,%3};"
        : "+f"(c[0]), "+f"(c[1]), "+f"(c[2]), "+f"(c[3])
        : "r"(a[0]), "r"(a[1]), "r"(a[2]), "r"(a[3]), "r"(b[0]), "r"(b[1]));
}

// ===========================================================================
// Prep (merged): blocks [0,4096) split x; blocks [4096,4352) combine weights
// ===========================================================================
__device__ __forceinline__ void bf16_split(float v, unsigned short& hi, unsigned short& lo) {
    __nv_bfloat16 h = __float2bfloat16(v);
    float r = v - __bfloat162float(h);
    hi = __bfloat16_as_ushort(h);
    lo = __bfloat16_as_ushort(__float2bfloat16(r));
}

__global__ void prep_kernel(const float* __restrict__ x,
                            const float* __restrict__ Wa, const float* __restrict__ Wp,
                            const float* __restrict__ Ws, const float* __restrict__ Wm,
                            const float* __restrict__ Wd) {
    if (blockIdx.x < 4096) {
        const int i = (blockIdx.x * 256 + threadIdx.x) * 4;
        float4 v = *reinterpret_cast<const float4*>(x + i);
        ushort4 h, l;
        bf16_split(v.x, h.x, l.x);
        bf16_split(v.y, h.y, l.y);
        bf16_split(v.z, h.z, l.z);
        bf16_split(v.w, h.w, l.w);
        *reinterpret_cast<ushort4*>(g_xhi + i) = h;
        *reinterpret_cast<ushort4*>(g_xlo + i) = l;
    } else {
        const int idx = (blockIdx.x - 4096) * 256 + threadIdx.x;  // idx = k*256 + n
        const int k = idx >> 8, n = idx & 255;
        const float p = Wp[idx], s = Ws[idx], m = Wm[idx], d = Wd[idx], a = Wa[idx];
        const float avg = 0.5f * (m + d);
        float vals[4] = {a, p + avg, s + avg, m - d};
        const int tr = n * DIM + k;
#pragma unroll
        for (int w = 0; w < 4; w++) {
            unsigned short hi, lo;
            bf16_split(vals[w], hi, lo);
            g_wthi[w * DIM * DIM + tr] = hi;
            g_wtlo[w * DIM * DIM + tr] = lo;
        }
    }
}

// ===========================================================================
// Warp-MMA bf16x3 GEMM (validated R10)
// ===========================================================================
#define KC     64
#define SSTR   72
#define TILEB  (128 * SSTR * 2)
#define SM_AHI 0
#define SM_ALO (TILEB)
#define SM_BHI (2 * TILEB)
#define SM_BLO (3 * TILEB)
#define SM_TOTAL (4 * TILEB)

__global__ void __launch_bounds__(256) gemm_tc_kernel() {
    extern __shared__ __align__(16) char smem[];
    const uint32_t sb = smem_to_u32(smem);
    const int tid  = threadIdx.x;
    const int wid  = tid >> 5;
    const int lane = tid & 31;

    const int row0  = blockIdx.x * 128;
    const int widx  = blockIdx.y >> 1;
    const int ncol0 = (blockIdx.y & 1) * 128;

    float* __restrict__ Cout = g_scratch + (size_t)widx * N_UTT * DIM;
    const unsigned short* __restrict__ wth = g_wthi + widx * DIM * DIM;
    const unsigned short* __restrict__ wtl = g_wtlo + widx * DIM * DIM;

    const int m0w = (wid & 1) * 64;
    const int n0w = (wid >> 1) * 32;

    float acc[4][4][4];
#pragma unroll
    for (int a = 0; a < 4; a++)
#pragma unroll
        for (int b = 0; b < 4; b++)
#pragma unroll
            for (int c = 0; c < 4; c++) acc[a][b][c] = 0.f;

    const uint32_t a_lane_off = (uint32_t)(((m0w + (lane & 15)) * SSTR + ((lane >> 4) << 3)) * 2);
    const uint32_t b_lane_off = (uint32_t)(((n0w + (lane & 7) + ((lane >> 4) << 3)) * SSTR + (lane & 8)) * 2);

    for (int c = 0; c < 4; c++) {
        const int k0 = c * KC;
        __syncthreads();
#pragma unroll
        for (int s = tid; s < 1024; s += 256) {
            const int r = s >> 3, f = s & 7;
            const uint32_t dst = (uint32_t)((r * SSTR + f * 8) * 2);
            const size_t src = (size_t)(row0 + r) * DIM + k0 + f * 8;
            *reinterpret_cast<uint4*>(smem + SM_AHI + dst) = *reinterpret_cast<const uint4*>(g_xhi + src);
            *reinterpret_cast<uint4*>(smem + SM_ALO + dst) = *reinterpret_cast<const uint4*>(g_xlo + src);
        }
#pragma unroll
        for (int s = tid; s < 1024; s += 256) {
            const int n = s >> 3, f = s & 7;
            const uint32_t dst = (uint32_t)((n * SSTR + f * 8) * 2);
            const size_t src = (size_t)(ncol0 + n) * DIM + k0 + f * 8;
            *reinterpret_cast<uint4*>(smem + SM_BHI + dst) = *reinterpret_cast<const uint4*>(wth + src);
            *reinterpret_cast<uint4*>(smem + SM_BLO + dst) = *reinterpret_cast<const uint4*>(wtl + src);
        }
        __syncthreads();

#pragma unroll
        for (int kk = 0; kk < KC; kk += 16) {
            const uint32_t kb = (uint32_t)(kk * 2);
            uint32_t ah[4][4], al[4][4], bh[2][4], bl[2][4];
#pragma unroll
            for (int mt = 0; mt < 4; mt++)
                ldsm_x4(ah[mt], sb + SM_AHI + a_lane_off + (uint32_t)(mt * 16 * SSTR * 2) + kb);
#pragma unroll
            for (int nt = 0; nt < 2; nt++)
                ldsm_x4(bh[nt], sb + SM_BHI + b_lane_off + (uint32_t)(nt * 16 * SSTR * 2) + kb);
#pragma unroll
            for (int mt = 0; mt < 4; mt++)
#pragma unroll
                for (int n8 = 0; n8 < 4; n8++)
                    mma16816(acc[mt][n8], ah[mt], &bh[n8 >> 1][(n8 & 1) * 2]);
#pragma unroll
            for (int nt = 0; nt < 2; nt++)
                ldsm_x4(bl[nt], sb + SM_BLO + b_lane_off + (uint32_t)(nt * 16 * SSTR * 2) + kb);
#pragma unroll
            for (int mt = 0; mt < 4; mt++)
#pragma unroll
                for (int n8 = 0; n8 < 4; n8++)
                    mma16816(acc[mt][n8], ah[mt], &bl[n8 >> 1][(n8 & 1) * 2]);
#pragma unroll
            for (int mt = 0; mt < 4; mt++)
                ldsm_x4(al[mt], sb + SM_ALO + a_lane_off + (uint32_t)(mt * 16 * SSTR * 2) + kb);
#pragma unroll
            for (int mt = 0; mt < 4; mt++)
#pragma unroll
                for (int n8 = 0; n8 < 4; n8++)
                    mma16816(acc[mt][n8], al[mt], &bh[n8 >> 1][(n8 & 1) * 2]);
        }
    }

    const int qr = lane >> 2, qc = (lane & 3) * 2;
#pragma unroll
    for (int mt = 0; mt < 4; mt++) {
        const int row = row0 + m0w + mt * 16 + qr;
#pragma unroll
        for (int n8 = 0; n8 < 4; n8++) {
            const int col = ncol0 + n0w + n8 * 8 + qc;
            *reinterpret_cast<float2*>(&Cout[(size_t)row * DIM + col]) =
                make_float2(acc[mt][n8][0], acc[mt][n8][1]);
            *reinterpret_cast<float2*>(&Cout[(size_t)(row + 8) * DIM + col]) =
                make_float2(acc[mt][n8][2], acc[mt][n8][3]);
        }
    }
}

// ===========================================================================
// Fused (G=16): MMA band attention + softmax + aggregation + log_softmax
// ===========================================================================
#define KCF     32
#define AW_STR  40           // window stride (bf16 words): 80B rows, conflict-free ldsm
#define Q_STR   264          // q stride (bf16 words): 528B rows, conflict-free ldsm
#define LOG_STR 17

#define OFF_AWH   0                       // 144*80  = 11520
#define OFF_AWL   11520                   // 11520  -> 23040
#define OFF_QH    23040                   // 16*528 = 8448
#define OFF_QL    31488                   // 8448   -> 39936
#define OFF_SLOG  39936                   // 144*17*4 = 9792 -> 49728
#define OFF_SATTN 49728                   // 16*128*4 = 8192 -> 57920
#define OFF_SPKW  57920                   // 144*4 = 576 -> 58496
#define OFF_SLSE  58496                   // 64
#define SMF_TOTAL 58560
// phase B aliases (over window/Q/slog region, dead after softmax)
#define OFF_CSAP  0                       // 143*16*4 = 9152
#define OFF_CSAS  9152
#define OFF_CSB   18304                   // -> 27456
#define OFF_SACC  27456                   // 16*256*4 = 16384 -> 43840 (< 49728)

__device__ __forceinline__ float warpMax(float v) {
#pragma unroll
    for (int o = 16; o > 0; o >>= 1) v = fmaxf(v, __shfl_xor_sync(0xffffffffu, v, o));
    return v;
}
__device__ __forceinline__ float warpSum(float v) {
#pragma unroll
    for (int o = 16; o > 0; o >>= 1) v += __shfl_xor_sync(0xffffffffu, v, o);
    return v;
}

__global__ __launch_bounds__(256) void fused_kernel(const int* __restrict__ spk,
                                                    float* __restrict__ out) {
    extern __shared__ __align__(16) char sm[];
    const uint32_t sb = smem_to_u32(sm);

    const int i0   = blockIdx.x * G;
    const int tid  = threadIdx.x;
    const int wi   = tid >> 5;
    const int lane = tid & 31;

    const float* __restrict__ Q   = g_scratch;
    const float* __restrict__ T1p = g_scratch + 1ULL * N_UTT * DIM;
    const float* __restrict__ T1s = g_scratch + 2ULL * N_UTT * DIM;
    const float* __restrict__ T2  = g_scratch + 3ULL * N_UTT * DIM;

    float* const slog  = reinterpret_cast<float*>(sm + OFF_SLOG);
    float* const sattn = reinterpret_cast<float*>(sm + OFF_SATTN);
    int*   const spkw  = reinterpret_cast<int*>(sm + OFF_SPKW);
    float* const slse  = reinterpret_cast<float*>(sm + OFF_SLSE);

    // ---- Q rows fp32 -> bf16 hi/lo in smem (16 rows x 256) ----
    {
        const int row = tid >> 4;
        const int c0  = (tid & 15) * 16;
        const float* qs = Q + (size_t)(i0 + row) * DIM + c0;
#pragma unroll
        for (int h = 0; h < 2; h++) {
            float4 v0 = *reinterpret_cast<const float4*>(qs + 8 * h);
            float4 v1 = *reinterpret_cast<const float4*>(qs + 8 * h + 4);
            unsigned short hh[8], ll[8];
            bf16_split(v0.x, hh[0], ll[0]); bf16_split(v0.y, hh[1], ll[1]);
            bf16_split(v0.z, hh[2], ll[2]); bf16_split(v0.w, hh[3], ll[3]);
            bf16_split(v1.x, hh[4], ll[4]); bf16_split(v1.y, hh[5], ll[5]);
            bf16_split(v1.z, hh[6], ll[6]); bf16_split(v1.w, hh[7], ll[7]);
            *reinterpret_cast<uint4*>(sm + OFF_QH + row * (Q_STR * 2) + (c0 + 8 * h) * 2) =
                *reinterpret_cast<uint4*>(hh);
            *reinterpret_cast<uint4*>(sm + OFF_QL + row * (Q_STR * 2) + (c0 + 8 * h) * 2) =
                *reinterpret_cast<uint4*>(ll);
        }
    }
    if (tid < NW) {
        int j = i0 + tid - WHALF;
        j = min(max(j, 0), N_UTT - 1);
        spkw[tid] = spk[j];
    }

    // ---- band QK^T via m16n8k16 bf16x3; B tile n=16 ----
    float facc[2][2][4];
#pragma unroll
    for (int t = 0; t < 2; t++)
#pragma unroll
        for (int n8 = 0; n8 < 2; n8++)
#pragma unroll
            for (int k = 0; k < 4; k++) facc[t][n8][k] = 0.f;

    const uint32_t aoff = (uint32_t)(((lane & 15) * AW_STR + ((lane >> 4) << 3)) * 2);
    const uint32_t boff = (uint32_t)((((lane & 7) + ((lane >> 4) << 3)) * Q_STR + (lane & 8)) * 2);

    for (int c = 0; c < 8; c++) {
        __syncthreads();
        for (int s = tid; s < 576; s += 256) {
            const int r = s >> 2, f = s & 3;
            const int j = i0 + r - WHALF;
            uint4 vh = make_uint4(0, 0, 0, 0), vl = make_uint4(0, 0, 0, 0);
            if (r < NW && j >= 0 && j < N_UTT) {
                const size_t src = (size_t)j * DIM + c * KCF + f * 8;
                vh = *reinterpret_cast<const uint4*>(g_xhi + src);
                vl = *reinterpret_cast<const uint4*>(g_xlo + src);
            }
            *reinterpret_cast<uint4*>(sm + OFF_AWH + r * (AW_STR * 2) + f * 16) = vh;
            *reinterpret_cast<uint4*>(sm + OFF_AWL + r * (AW_STR * 2) + f * 16) = vl;
        }
        __syncthreads();
#pragma unroll
        for (int ks = 0; ks < 2; ks++) {
            uint32_t bh[4], bl[4];
            const uint32_t kqb = (uint32_t)(c * KCF + ks * 16) * 2;
            ldsm_x4(bh, sb + OFF_QH + boff + kqb);
            ldsm_x4(bl, sb + OFF_QL + boff + kqb);
            int ti = 0;
            for (int mt = wi; mt < 9; mt += 8, ti++) {
                uint32_t ah[4], al[4];
                const uint32_t mtoff = (uint32_t)(mt * 16 * AW_STR * 2) + (uint32_t)(ks * 32);
                ldsm_x4(ah, sb + OFF_AWH + mtoff + aoff);
                ldsm_x4(al, sb + OFF_AWL + mtoff + aoff);
#pragma unroll
                for (int n8 = 0; n8 < 2; n8++) {
                    mma16816(facc[ti][n8], ah, &bh[n8 * 2]);
                    mma16816(facc[ti][n8], ah, &bl[n8 * 2]);
                    mma16816(facc[ti][n8], al, &bh[n8 * 2]);
                }
            }
        }
    }
    // fragments -> slog[row][li], stride 17
    {
        const int qr = lane >> 2, qc = (lane & 3) * 2;
        int ti = 0;
        for (int mt = wi; mt < 9; mt += 8, ti++) {
            const int r = mt * 16 + qr;
#pragma unroll
            for (int n8 = 0; n8 < 2; n8++) {
                const int col = n8 * 8 + qc;
                slog[r * LOG_STR + col]           = facc[ti][n8][0];
                slog[r * LOG_STR + col + 1]       = facc[ti][n8][1];
                slog[(r + 8) * LOG_STR + col]     = facc[ti][n8][2];
                slog[(r + 8) * LOG_STR + col + 1] = facc[ti][n8][3];
            }
        }
    }
    __syncthreads();

    // ---- softmax: warp wi owns rows wi and wi+8 ----
#pragma unroll
    for (int rr = 0; rr < 2; rr++) {
        const int li = wi + rr * 8;
        const int i  = i0 + li;
        float v0 = slog[(li + lane) * LOG_STR + li];
        float v1 = slog[(li + lane + 32) * LOG_STR + li];
        float v2 = slog[(li + lane + 64) * LOG_STR + li];
        float v3 = slog[(li + lane + 96) * LOG_STR + li];
        float m = warpMax(fmaxf(fmaxf(v0, v1), fmaxf(v2, v3)));
        const float e0 = __expf(v0 - m), e1 = __expf(v1 - m),
                    e2 = __expf(v2 - m), e3 = __expf(v3 - m);
        const float inv = 1.f / warpSum(e0 + e1 + e2 + e3);
        int j;
        j = i + lane - WHALF;       sattn[li * WIN + lane]      = (j >= 0 && j < N_UTT) ? e0 * inv : 0.f;
        j = i + lane - WHALF + 32;  sattn[li * WIN + lane + 32] = (j >= 0 && j < N_UTT) ? e1 * inv : 0.f;
        j = i + lane - WHALF + 64;  sattn[li * WIN + lane + 64] = (j >= 0 && j < N_UTT) ? e2 * inv : 0.f;
        j = i + lane - WHALF + 96;  sattn[li * WIN + lane + 96] = (j >= 0 && j < N_UTT) ? e3 * inv : 0.f;
    }
    __syncthreads();

    // ---- coefficient tables [jj][li=16] ----
    float* const csAp = reinterpret_cast<float*>(sm + OFF_CSAP);
    float* const csAs = reinterpret_cast<float*>(sm + OFF_CSAS);
    float* const csB  = reinterpret_cast<float*>(sm + OFF_CSB);
    for (int t = tid; t < NW * G; t += 256) {
        const int jj = t >> 4, li = t & 15;
        const int w = jj - li;
        const float c = (w >= 0 && w < WIN) ? sattn[li * WIN + w] : 0.f;
        csAp[t] = (w >= WHALF) ? c : 0.f;
        csAs[t] = (w < WHALF) ? c : 0.f;
        csB[t]  = (spkw[jj] == spkw[WHALF + li]) ? 0.5f * c : -0.5f * c;
    }
    __syncthreads();

    // ---- aggregation: thread owns feature d, 16 accumulators ----
    const int d = tid;
    float acc[G];
#pragma unroll
    for (int li = 0; li < G; li++) acc[li] = 0.f;

    const int jlo = (i0 < WHALF) ? (WHALF - i0) : 0;
    const int jhi = min(NW, N_UTT - i0 + WHALF);

#define AGGH(AV, BV, HB, T1V, T2V)                                                   \
    do {                                                                             \
        const float4 a0 = *reinterpret_cast<const float4*>(&(AV)[jj * 16 + (HB)]);   \
        const float4 a1 = *reinterpret_cast<const float4*>(&(AV)[jj * 16 + (HB) + 4]);\
        const float4 b0 = *reinterpret_cast<const float4*>(&(BV)[jj * 16 + (HB)]);   \
        const float4 b1 = *reinterpret_cast<const float4*>(&(BV)[jj * 16 + (HB) + 4]);\
        acc[(HB) + 0] = fmaf(a0.x, (T1V), fmaf(b0.x, (T2V), acc[(HB) + 0]));         \
        acc[(HB) + 1] = fmaf(a0.y, (T1V), fmaf(b0.y, (T2V), acc[(HB) + 1]));         \
        acc[(HB) + 2] = fmaf(a0.z, (T1V), fmaf(b0.z, (T2V), acc[(HB) + 2]));         \
        acc[(HB) + 3] = fmaf(a0.w, (T1V), fmaf(b0.w, (T2V), acc[(HB) + 3]));         \
        acc[(HB) + 4] = fmaf(a1.x, (T1V), fmaf(b1.x, (T2V), acc[(HB) + 4]));         \
        acc[(HB) + 5] = fmaf(a1.y, (T1V), fmaf(b1.y, (T2V), acc[(HB) + 5]));         \
        acc[(HB) + 6] = fmaf(a1.z, (T1V), fmaf(b1.z, (T2V), acc[(HB) + 6]));         \
        acc[(HB) + 7] = fmaf(a1.w, (T1V), fmaf(b1.w, (T2V), acc[(HB) + 7]));         \
    } while (0)

#pragma unroll 4
    for (int jj = jlo; jj < WHALF; jj++) {
        const size_t off = (size_t)(i0 + jj - WHALF) * DIM + d;
        const float t1 = T1s[off], t2 = T2[off];
        AGGH(csAs, csB, 0, t1, t2);
        AGGH(csAs, csB, 8, t1, t2);
    }
    for (int jj = WHALF; jj < WHALF + G - 1; jj++) {
        const size_t off = (size_t)(i0 + jj - WHALF) * DIM + d;
        const float t1p = T1p[off], t1s = T1s[off], t2 = T2[off];
#pragma unroll
        for (int hb = 0; hb < 16; hb += 8) {
            const float4 p0 = *reinterpret_cast<const float4*>(&csAp[jj * 16 + hb]);
            const float4 p1 = *reinterpret_cast<const float4*>(&csAp[jj * 16 + hb + 4]);
            const float4 s0 = *reinterpret_cast<const float4*>(&csAs[jj * 16 + hb]);
            const float4 s1 = *reinterpret_cast<const float4*>(&csAs[jj * 16 + hb + 4]);
            const float4 b0 = *reinterpret_cast<const float4*>(&csB[jj * 16 + hb]);
            const float4 b1 = *reinterpret_cast<const float4*>(&csB[jj * 16 + hb + 4]);
            acc[hb + 0] = fmaf(p0.x, t1p, fmaf(s0.x, t1s, fmaf(b0.x, t2, acc[hb + 0])));
            acc[hb + 1] = fmaf(p0.y, t1p, fmaf(s0.y, t1s, fmaf(b0.y, t2, acc[hb + 1])));
            acc[hb + 2] = fmaf(p0.z, t1p, fmaf(s0.z, t1s, fmaf(b0.z, t2, acc[hb + 2])));
            acc[hb + 3] = fmaf(p0.w, t1p, fmaf(s0.w, t1s, fmaf(b0.w, t2, acc[hb + 3])));
            acc[hb + 4] = fmaf(p1.x, t1p, fmaf(s1.x, t1s, fmaf(b1.x, t2, acc[hb + 4])));
            acc[hb + 5] = fmaf(p1.y, t1p, fmaf(s1.y, t1s, fmaf(b1.y, t2, acc[hb + 5])));
            acc[hb + 6] = fmaf(p1.z, t1p, fmaf(s1.z, t1s, fmaf(b1.z, t2, acc[hb + 6])));
            acc[hb + 7] = fmaf(p1.w, t1p, fmaf(s1.w, t1s, fmaf(b1.w, t2, acc[hb + 7])));
        }
    }
#pragma unroll 4
    for (int jj = WHALF + G - 1; jj < jhi; jj++) {
        const size_t off = (size_t)(i0 + jj - WHALF) * DIM + d;
        const float t1 = T1p[off], t2 = T2[off];
        AGGH(csAp, csB, 0, t1, t2);
        AGGH(csAp, csB, 8, t1, t2);
    }

    // ---- log_softmax over D (transposed reduction, 2 rows per warp) ----
    float* const s_acc = reinterpret_cast<float*>(sm + OFF_SACC);
    __syncthreads();
#pragma unroll
    for (int li = 0; li < G; li++) s_acc[li * DIM + d] = acc[li];
    __syncthreads();
#pragma unroll
    for (int rr = 0; rr < 2; rr++) {
        const int r = wi + rr * 8;
        float v[8];
#pragma unroll
        for (int k = 0; k < 8; k++) v[k] = s_acc[r * DIM + lane + 32 * k];
        float m = v[0];
#pragma unroll
        for (int k = 1; k < 8; k++) m = fmaxf(m, v[k]);
        m = warpMax(m);
        float s = 0.f;
#pragma unroll
        for (int k = 0; k < 8; k++) s += __expf(v[k] - m);
        s = warpSum(s);
        if (lane == 0) slse[r] = m + logf(s);
    }
    __syncthreads();
#pragma unroll
    for (int li = 0; li < G; li++)
        out[(size_t)(i0 + li) * DIM + d] = acc[li] - slse[li];
}

// ---------------------------------------------------------------------------
extern "C" void kernel_launch(void* const* d_in, const int* in_sizes, int n_in,
                              void* d_out, int out_size) {
    const float* x   = (const float*)d_in[0];
    const int*   spk = (const int*)d_in[1];
    const float* Wa  = (const float*)d_in[2];
    const float* Wp  = (const float*)d_in[3];
    const float* Ws  = (const float*)d_in[4];
    const float* Wm  = (const float*)d_in[5];
    const float* Wd  = (const float*)d_in[6];
    float* out = (float*)d_out;

    cudaFuncSetAttribute(gemm_tc_kernel, cudaFuncAttributeMaxDynamicSharedMemorySize, SM_TOTAL);
    cudaFuncSetAttribute(fused_kernel, cudaFuncAttributeMaxDynamicSharedMemorySize, SMF_TOTAL);

    prep_kernel<<<4096 + 256, 256>>>(x, Wa, Wp, Ws, Wm, Wd);
    gemm_tc_kernel<<<dim3(N_UTT / 128, 8), 256, SM_TOTAL>>>();
    fused_kernel<<<N_UTT / G, 256, SMF_TOTAL>>>(spk, out);
}

// round 13
// speedup vs baseline: 1.0100x; 1.0100x over previous
#include <cuda_runtime.h>
#include <cuda_bf16.h>
#include <cstdint>

#define N_UTT 16384
#define DIM   256
#define WHALF 64
#define WIN   128
#define G     16
#define NW    143            // WIN + G - 1
#define NPAD  144

// Scratch: [0]=Q=x@W_att, [1]=T1p=x@Wc1, [2]=T1s=x@Wc2, [3]=T2=x@Wc3
__device__ float g_scratch[4ULL * N_UTT * DIM];
__device__ __align__(16) unsigned short g_xhi[N_UTT * DIM];
__device__ __align__(16) unsigned short g_xlo[N_UTT * DIM];
__device__ __align__(16) unsigned short g_wthi[4 * DIM * DIM];
__device__ __align__(16) unsigned short g_wtlo[4 * DIM * DIM];

__device__ __forceinline__ uint32_t smem_to_u32(const void* p) {
    uint32_t a;
    asm("{ .reg .u64 t; cvta.to.shared.u64 t, %1; cvt.u32.u64 %0, t; }" : "=r"(a) : "l"(p));
    return a;
}
__device__ __forceinline__ void ldsm_x4(uint32_t* r, uint32_t addr) {
    asm volatile("ldmatrix.sync.aligned.m8n8.x4.shared.b16 {%0,%1,%2,%3}, [%4];"
                 : "=r"(r[0]), "=r"(r[1]), "=r"(r[2]), "=r"(r[3]) : "r"(addr));
}
__device__ __forceinline__ void mma16816(float* c, const uint32_t* a, const uint32_t* b) {
    asm volatile(
        "mma.sync.aligned.m16n8k16.row.col.f32.bf16.bf16.f32 "
        "{%0,%1,%2,%3}, {%4,%5,%6,%7}, {%8,%9}, {%0,%1,%2,%3};"
        : "+f"(c[0]), "+f"(c[1]), "+f"(c[2]), "+f"(c[3])
        : "r"(a[0]), "r"(a[1]), "r"(a[2]), "r"(a[3]), "r"(b[0]), "r"(b[1]));
}
__device__ __forceinline__ void cp_async16(uint32_t dst, const void* src) {
    asm volatile("cp.async.ca.shared.global [%0], [%1], 16;" :: "r"(dst), "l"(src));
}
#define CP_COMMIT()  asm volatile("cp.async.commit_group;" ::: "memory")
#define CP_WAIT(N)   asm volatile("cp.async.wait_group %0;" :: "n"(N) : "memory")

// ===========================================================================
// Prep kernels
// ===========================================================================
__device__ __forceinline__ void bf16_split(float v, unsigned short& hi, unsigned short& lo) {
    __nv_bfloat16 h = __float2bfloat16(v);
    float r = v - __bfloat162float(h);
    hi = __bfloat16_as_ushort(h);
    lo = __bfloat16_as_ushort(__float2bfloat16(r));
}

__global__ void split_x_kernel(const float* __restrict__ x) {
    const int i = (blockIdx.x * 256 + threadIdx.x) * 8;
    float4 v0 = *reinterpret_cast<const float4*>(x + i);
    float4 v1 = *reinterpret_cast<const float4*>(x + i + 4);
    ushort4 h0, l0, h1, l1;
    bf16_split(v0.x, h0.x, l0.x); bf16_split(v0.y, h0.y, l0.y);
    bf16_split(v0.z, h0.z, l0.z); bf16_split(v0.w, h0.w, l0.w);
    bf16_split(v1.x, h1.x, l1.x); bf16_split(v1.y, h1.y, l1.y);
    bf16_split(v1.z, h1.z, l1.z); bf16_split(v1.w, h1.w, l1.w);
    *reinterpret_cast<ushort4*>(g_xhi + i)     = h0;
    *reinterpret_cast<ushort4*>(g_xhi + i + 4) = h1;
    *reinterpret_cast<ushort4*>(g_xlo + i)     = l0;
    *reinterpret_cast<ushort4*>(g_xlo + i + 4) = l1;
}

__global__ void prep_w_kernel(const float* __restrict__ Wa, const float* __restrict__ Wp,
                              const float* __restrict__ Ws, const float* __restrict__ Wm,
                              const float* __restrict__ Wd) {
    const int idx = blockIdx.x * 256 + threadIdx.x;  // idx = k*256 + n
    const int k = idx >> 8, n = idx & 255;
    const float p = Wp[idx], s = Ws[idx], m = Wm[idx], d = Wd[idx], a = Wa[idx];
    const float avg = 0.5f * (m + d);
    float vals[4] = {a, p + avg, s + avg, m - d};
    const int tr = n * DIM + k;
#pragma unroll
    for (int w = 0; w < 4; w++) {
        unsigned short hi, lo;
        bf16_split(vals[w], hi, lo);
        g_wthi[w * DIM * DIM + tr] = hi;
        g_wtlo[w * DIM * DIM + tr] = lo;
    }
}

// ===========================================================================
// Warp-MMA bf16x3 GEMM, cp.async double-buffered, KC=32
// grid (128, 8): y = widx*2 + ncol-half
// ===========================================================================
#define GKC     32
#define GSTR    40                    // bf16 words per row (80B) — conflict-free ldsm
#define GTILE   (128 * GSTR * 2)      // 10240 B
#define OFF_GAH 0
#define OFF_GAL (GTILE)
#define OFF_GBH (2 * GTILE)
#define OFF_GBL (3 * GTILE)
#define GSTAGE  (4 * GTILE)           // 40960
#define GSM_TOTAL (2 * GSTAGE)        // 81920

__global__ void __launch_bounds__(256) gemm_tc_kernel() {
    extern __shared__ __align__(16) char smem[];
    const uint32_t sb = smem_to_u32(smem);
    const int tid  = threadIdx.x;
    const int wid  = tid >> 5;
    const int lane = tid & 31;

    const int row0  = blockIdx.x * 128;
    const int widx  = blockIdx.y >> 1;
    const int ncol0 = (blockIdx.y & 1) * 128;

    float* __restrict__ Cout = g_scratch + (size_t)widx * N_UTT * DIM;
    const unsigned short* __restrict__ wth = g_wthi + widx * DIM * DIM;
    const unsigned short* __restrict__ wtl = g_wtlo + widx * DIM * DIM;

    const int m0w = (wid & 1) * 64;
    const int n0w = (wid >> 1) * 32;

    float acc[4][4][4];
#pragma unroll
    for (int a = 0; a < 4; a++)
#pragma unroll
        for (int b = 0; b < 4; b++)
#pragma unroll
            for (int c = 0; c < 4; c++) acc[a][b][c] = 0.f;

    const uint32_t a_lane_off = (uint32_t)((m0w + (lane & 15)) * 80 + (lane >> 4) * 16);
    const uint32_t b_lane_off = (uint32_t)((n0w + (lane & 7) + ((lane >> 4) << 3)) * 80 + (lane & 8) * 2);

    // staging lane mapping (fixed per thread): 512 (r,f) pairs per tile
    const int r0s = tid >> 2, f0s = tid & 3;          // q=0
    const int r1s = (tid + 256) >> 2, f1s = tid & 3;  // q=1

#define GPREFETCH(CIDX, ST)                                                              \
    do {                                                                                 \
        const int _k0 = (CIDX) * GKC;                                                    \
        const uint32_t _sbase = sb + (ST) * GSTAGE;                                      \
        {                                                                                \
            const uint32_t _do = (uint32_t)(r0s * 80 + f0s * 16);                        \
            const size_t _sa = (size_t)(row0 + r0s) * DIM + _k0 + f0s * 8;               \
            const size_t _sbv = (size_t)(ncol0 + r0s) * DIM + _k0 + f0s * 8;             \
            cp_async16(_sbase + OFF_GAH + _do, g_xhi + _sa);                             \
            cp_async16(_sbase + OFF_GAL + _do, g_xlo + _sa);                             \
            cp_async16(_sbase + OFF_GBH + _do, wth + _sbv);                              \
            cp_async16(_sbase + OFF_GBL + _do, wtl + _sbv);                              \
        }                                                                                \
        {                                                                                \
            const uint32_t _do = (uint32_t)(r1s * 80 + f1s * 16);                        \
            const size_t _sa = (size_t)(row0 + r1s) * DIM + _k0 + f1s * 8;               \
            const size_t _sbv = (size_t)(ncol0 + r1s) * DIM + _k0 + f1s * 8;             \
            cp_async16(_sbase + OFF_GAH + _do, g_xhi + _sa);                             \
            cp_async16(_sbase + OFF_GAL + _do, g_xlo + _sa);                             \
            cp_async16(_sbase + OFF_GBH + _do, wth + _sbv);                              \
            cp_async16(_sbase + OFF_GBL + _do, wtl + _sbv);                              \
        }                                                                                \
    } while (0)

    GPREFETCH(0, 0); CP_COMMIT();
    GPREFETCH(1, 1); CP_COMMIT();
    CP_WAIT(1);
    __syncthreads();   // stage 0 visible to all

    for (int c = 0; c < 8; c++) {
        const uint32_t sst = sb + (c & 1) * GSTAGE;
#pragma unroll
        for (int ks = 0; ks < 2; ks++) {
            const uint32_t kb = (uint32_t)(ks * 32);
            uint32_t bh[2][4], bl[2][4];
#pragma unroll
            for (int nt = 0; nt < 2; nt++) {
                ldsm_x4(bh[nt], sst + OFF_GBH + b_lane_off + (uint32_t)(nt * 16 * 80) + kb);
                ldsm_x4(bl[nt], sst + OFF_GBL + b_lane_off + (uint32_t)(nt * 16 * 80) + kb);
            }
#pragma unroll
            for (int mt = 0; mt < 4; mt++) {
                uint32_t ah[4], al[4];
                const uint32_t mto = (uint32_t)(mt * 16 * 80) + kb;
                ldsm_x4(ah, sst + OFF_GAH + a_lane_off + mto);
                ldsm_x4(al, sst + OFF_GAL + a_lane_off + mto);
#pragma unroll
                for (int n8 = 0; n8 < 4; n8++) {
                    mma16816(acc[mt][n8], ah, &bh[n8 >> 1][(n8 & 1) * 2]);
                    mma16816(acc[mt][n8], ah, &bl[n8 >> 1][(n8 & 1) * 2]);
                    mma16816(acc[mt][n8], al, &bh[n8 >> 1][(n8 & 1) * 2]);
                }
            }
        }
        __syncthreads();   // all warps done reading this stage
        if (c + 2 < 8) { GPREFETCH(c + 2, c & 1); CP_COMMIT(); }
        if (c + 1 < 8) {
            if (c + 2 < 8) CP_WAIT(1);
            else           CP_WAIT(0);
            __syncthreads();
        }
    }

    const int qr = lane >> 2, qc = (lane & 3) * 2;
#pragma unroll
    for (int mt = 0; mt < 4; mt++) {
        const int row = row0 + m0w + mt * 16 + qr;
#pragma unroll
        for (int n8 = 0; n8 < 4; n8++) {
            const int col = ncol0 + n0w + n8 * 8 + qc;
            *reinterpret_cast<float2*>(&Cout[(size_t)row * DIM + col]) =
                make_float2(acc[mt][n8][0], acc[mt][n8][1]);
            *reinterpret_cast<float2*>(&Cout[(size_t)(row + 8) * DIM + col]) =
                make_float2(acc[mt][n8][2], acc[mt][n8][3]);
        }
    }
}

// ===========================================================================
// Fused (G=16): MMA band attention + softmax + aggregation + log_softmax
// ===========================================================================
#define KCF     32
#define AW_STR  40
#define Q_STR   264
#define LOG_STR 17

#define OFF_AWH   0
#define OFF_AWL   11520
#define OFF_QH    23040
#define OFF_QL    31488
#define OFF_SLOG  39936
#define OFF_SATTN 49728
#define OFF_SPKW  57920
#define OFF_SLSE  58496
#define SMF_TOTAL 58560
#define OFF_CSAP  0
#define OFF_CSAS  9152
#define OFF_CSB   18304
#define OFF_SACC  27456

__device__ __forceinline__ float warpMax(float v) {
#pragma unroll
    for (int o = 16; o > 0; o >>= 1) v = fmaxf(v, __shfl_xor_sync(0xffffffffu, v, o));
    return v;
}
__device__ __forceinline__ float warpSum(float v) {
#pragma unroll
    for (int o = 16; o > 0; o >>= 1) v += __shfl_xor_sync(0xffffffffu, v, o);
    return v;
}

__global__ __launch_bounds__(256) void fused_kernel(const int* __restrict__ spk,
                                                    float* __restrict__ out) {
    extern __shared__ __align__(16) char sm[];
    const uint32_t sb = smem_to_u32(sm);

    const int i0   = blockIdx.x * G;
    const int tid  = threadIdx.x;
    const int wi   = tid >> 5;
    const int lane = tid & 31;

    const float* __restrict__ Q   = g_scratch;
    const float* __restrict__ T1p = g_scratch + 1ULL * N_UTT * DIM;
    const float* __restrict__ T1s = g_scratch + 2ULL * N_UTT * DIM;
    const float* __restrict__ T2  = g_scratch + 3ULL * N_UTT * DIM;

    float* const slog  = reinterpret_cast<float*>(sm + OFF_SLOG);
    float* const sattn = reinterpret_cast<float*>(sm + OFF_SATTN);
    int*   const spkw  = reinterpret_cast<int*>(sm + OFF_SPKW);
    float* const slse  = reinterpret_cast<float*>(sm + OFF_SLSE);

    // ---- Q rows fp32 -> bf16 hi/lo in smem ----
    {
        const int row = tid >> 4;
        const int c0  = (tid & 15) * 16;
        const float* qs = Q + (size_t)(i0 + row) * DIM + c0;
#pragma unroll
        for (int h = 0; h < 2; h++) {
            float4 v0 = *reinterpret_cast<const float4*>(qs + 8 * h);
            float4 v1 = *reinterpret_cast<const float4*>(qs + 8 * h + 4);
            unsigned short hh[8], ll[8];
            bf16_split(v0.x, hh[0], ll[0]); bf16_split(v0.y, hh[1], ll[1]);
            bf16_split(v0.z, hh[2], ll[2]); bf16_split(v0.w, hh[3], ll[3]);
            bf16_split(v1.x, hh[4], ll[4]); bf16_split(v1.y, hh[5], ll[5]);
            bf16_split(v1.z, hh[6], ll[6]); bf16_split(v1.w, hh[7], ll[7]);
            *reinterpret_cast<uint4*>(sm + OFF_QH + row * (Q_STR * 2) + (c0 + 8 * h) * 2) =
                *reinterpret_cast<uint4*>(hh);
            *reinterpret_cast<uint4*>(sm + OFF_QL + row * (Q_STR * 2) + (c0 + 8 * h) * 2) =
                *reinterpret_cast<uint4*>(ll);
        }
    }
    if (tid < NW) {
        int j = i0 + tid - WHALF;
        j = min(max(j, 0), N_UTT - 1);
        spkw[tid] = spk[j];
    }

    // ---- band QK^T via m16n8k16 bf16x3; B tile n=16 ----
    float facc[2][2][4];
#pragma unroll
    for (int t = 0; t < 2; t++)
#pragma unroll
        for (int n8 = 0; n8 < 2; n8++)
#pragma unroll
            for (int k = 0; k < 4; k++) facc[t][n8][k] = 0.f;

    const uint32_t aoff = (uint32_t)(((lane & 15) * AW_STR + ((lane >> 4) << 3)) * 2);
    const uint32_t boff = (uint32_t)((((lane & 7) + ((lane >> 4) << 3)) * Q_STR + (lane & 8)) * 2);

    for (int c = 0; c < 8; c++) {
        __syncthreads();
        for (int s = tid; s < 576; s += 256) {
            const int r = s >> 2, f = s & 3;
            const int j = i0 + r - WHALF;
            uint4 vh = make_uint4(0, 0, 0, 0), vl = make_uint4(0, 0, 0, 0);
            if (r < NW && j >= 0 && j < N_UTT) {
                const size_t src = (size_t)j * DIM + c * KCF + f * 8;
                vh = *reinterpret_cast<const uint4*>(g_xhi + src);
                vl = *reinterpret_cast<const uint4*>(g_xlo + src);
            }
            *reinterpret_cast<uint4*>(sm + OFF_AWH + r * (AW_STR * 2) + f * 16) = vh;
            *reinterpret_cast<uint4*>(sm + OFF_AWL + r * (AW_STR * 2) + f * 16) = vl;
        }
        __syncthreads();
#pragma unroll
        for (int ks = 0; ks < 2; ks++) {
            uint32_t bh[4], bl[4];
            const uint32_t kqb = (uint32_t)(c * KCF + ks * 16) * 2;
            ldsm_x4(bh, sb + OFF_QH + boff + kqb);
            ldsm_x4(bl, sb + OFF_QL + boff + kqb);
            int ti = 0;
            for (int mt = wi; mt < 9; mt += 8, ti++) {
                uint32_t ah[4], al[4];
                const uint32_t mtoff = (uint32_t)(mt * 16 * AW_STR * 2) + (uint32_t)(ks * 32);
                ldsm_x4(ah, sb + OFF_AWH + mtoff + aoff);
                ldsm_x4(al, sb + OFF_AWL + mtoff + aoff);
#pragma unroll
                for (int n8 = 0; n8 < 2; n8++) {
                    mma16816(facc[ti][n8], ah, &bh[n8 * 2]);
                    mma16816(facc[ti][n8], ah, &bl[n8 * 2]);
                    mma16816(facc[ti][n8], al, &bh[n8 * 2]);
                }
            }
        }
    }
    {
        const int qr = lane >> 2, qc = (lane & 3) * 2;
        int ti = 0;
        for (int mt = wi; mt < 9; mt += 8, ti++) {
            const int r = mt * 16 + qr;
#pragma unroll
            for (int n8 = 0; n8 < 2; n8++) {
                const int col = n8 * 8 + qc;
                slog[r * LOG_STR + col]           = facc[ti][n8][0];
                slog[r * LOG_STR + col + 1]       = facc[ti][n8][1];
                slog[(r + 8) * LOG_STR + col]     = facc[ti][n8][2];
                slog[(r + 8) * LOG_STR + col + 1] = facc[ti][n8][3];
            }
        }
    }
    __syncthreads();

    // ---- softmax: warp wi owns rows wi and wi+8 ----
#pragma unroll
    for (int rr = 0; rr < 2; rr++) {
        const int li = wi + rr * 8;
        const int i  = i0 + li;
        float v0 = slog[(li + lane) * LOG_STR + li];
        float v1 = slog[(li + lane + 32) * LOG_STR + li];
        float v2 = slog[(li + lane + 64) * LOG_STR + li];
        float v3 = slog[(li + lane + 96) * LOG_STR + li];
        float m = warpMax(fmaxf(fmaxf(v0, v1), fmaxf(v2, v3)));
        const float e0 = __expf(v0 - m), e1 = __expf(v1 - m),
                    e2 = __expf(v2 - m), e3 = __expf(v3 - m);
        const float inv = 1.f / warpSum(e0 + e1 + e2 + e3);
        int j;
        j = i + lane - WHALF;       sattn[li * WIN + lane]      = (j >= 0 && j < N_UTT) ? e0 * inv : 0.f;
        j = i + lane - WHALF + 32;  sattn[li * WIN + lane + 32] = (j >= 0 && j < N_UTT) ? e1 * inv : 0.f;
        j = i + lane - WHALF + 64;  sattn[li * WIN + lane + 64] = (j >= 0 && j < N_UTT) ? e2 * inv : 0.f;
        j = i + lane - WHALF + 96;  sattn[li * WIN + lane + 96] = (j >= 0 && j < N_UTT) ? e3 * inv : 0.f;
    }
    __syncthreads();

    // ---- coefficient tables [jj][li=16] ----
    float* const csAp = reinterpret_cast<float*>(sm + OFF_CSAP);
    float* const csAs = reinterpret_cast<float*>(sm + OFF_CSAS);
    float* const csB  = reinterpret_cast<float*>(sm + OFF_CSB);
    for (int t = tid; t < NW * G; t += 256) {
        const int jj = t >> 4, li = t & 15;
        const int w = jj - li;
        const float c = (w >= 0 && w < WIN) ? sattn[li * WIN + w] : 0.f;
        csAp[t] = (w >= WHALF) ? c : 0.f;
        csAs[t] = (w < WHALF) ? c : 0.f;
        csB[t]  = (spkw[jj] == spkw[WHALF + li]) ? 0.5f * c : -0.5f * c;
    }
    __syncthreads();

    // ---- aggregation ----
    const int d = tid;
    float acc[G];
#pragma unroll
    for (int li = 0; li < G; li++) acc[li] = 0.f;

    const int jlo = (i0 < WHALF) ? (WHALF - i0) : 0;
    const int jhi = min(NW, N_UTT - i0 + WHALF);

#define AGGH(AV, BV, HB, T1V, T2V)                                                   \
    do {                                                                             \
        const float4 a0 = *reinterpret_cast<const float4*>(&(AV)[jj * 16 + (HB)]);   \
        const float4 a1 = *reinterpret_cast<const float4*>(&(AV)[jj * 16 + (HB) + 4]);\
        const float4 b0 = *reinterpret_cast<const float4*>(&(BV)[jj * 16 + (HB)]);   \
        const float4 b1 = *reinterpret_cast<const float4*>(&(BV)[jj * 16 + (HB) + 4]);\
        acc[(HB) + 0] = fmaf(a0.x, (T1V), fmaf(b0.x, (T2V), acc[(HB) + 0]));         \
        acc[(HB) + 1] = fmaf(a0.y, (T1V), fmaf(b0.y, (T2V), acc[(HB) + 1]));         \
        acc[(HB) + 2] = fmaf(a0.z, (T1V), fmaf(b0.z, (T2V), acc[(HB) + 2]));         \
        acc[(HB) + 3] = fmaf(a0.w, (T1V), fmaf(b0.w, (T2V), acc[(HB) + 3]));         \
        acc[(HB) + 4] = fmaf(a1.x, (T1V), fmaf(b1.x, (T2V), acc[(HB) + 4]));         \
        acc[(HB) + 5] = fmaf(a1.y, (T1V), fmaf(b1.y, (T2V), acc[(HB) + 5]));         \
        acc[(HB) + 6] = fmaf(a1.z, (T1V), fmaf(b1.z, (T2V), acc[(HB) + 6]));         \
        acc[(HB) + 7] = fmaf(a1.w, (T1V), fmaf(b1.w, (T2V), acc[(HB) + 7]));         \
    } while (0)

#pragma unroll 4
    for (int jj = jlo; jj < WHALF; jj++) {
        const size_t off = (size_t)(i0 + jj - WHALF) * DIM + d;
        const float t1 = T1s[off], t2 = T2[off];
        AGGH(csAs, csB, 0, t1, t2);
        AGGH(csAs, csB, 8, t1, t2);
    }
    for (int jj = WHALF; jj < WHALF + G - 1; jj++) {
        const size_t off = (size_t)(i0 + jj - WHALF) * DIM + d;
        const float t1p = T1p[off], t1s = T1s[off], t2 = T2[off];
#pragma unroll
        for (int hb = 0; hb < 16; hb += 8) {
            const float4 p0 = *reinterpret_cast<const float4*>(&csAp[jj * 16 + hb]);
            const float4 p1 = *reinterpret_cast<const float4*>(&csAp[jj * 16 + hb + 4]);
            const float4 s0 = *reinterpret_cast<const float4*>(&csAs[jj * 16 + hb]);
            const float4 s1 = *reinterpret_cast<const float4*>(&csAs[jj * 16 + hb + 4]);
            const float4 b0 = *reinterpret_cast<const float4*>(&csB[jj * 16 + hb]);
            const float4 b1 = *reinterpret_cast<const float4*>(&csB[jj * 16 + hb + 4]);
            acc[hb + 0] = fmaf(p0.x, t1p, fmaf(s0.x, t1s, fmaf(b0.x, t2, acc[hb + 0])));
            acc[hb + 1] = fmaf(p0.y, t1p, fmaf(s0.y, t1s, fmaf(b0.y, t2, acc[hb + 1])));
            acc[hb + 2] = fmaf(p0.z, t1p, fmaf(s0.z, t1s, fmaf(b0.z, t2, acc[hb + 2])));
            acc[hb + 3] = fmaf(p0.w, t1p, fmaf(s0.w, t1s, fmaf(b0.w, t2, acc[hb + 3])));
            acc[hb + 4] = fmaf(p1.x, t1p, fmaf(s1.x, t1s, fmaf(b1.x, t2, acc[hb + 4])));
            acc[hb + 5] = fmaf(p1.y, t1p, fmaf(s1.y, t1s, fmaf(b1.y, t2, acc[hb + 5])));
            acc[hb + 6] = fmaf(p1.z, t1p, fmaf(s1.z, t1s, fmaf(b1.z, t2, acc[hb + 6])));
            acc[hb + 7] = fmaf(p1.w, t1p, fmaf(s1.w, t1s, fmaf(b1.w, t2, acc[hb + 7])));
        }
    }
#pragma unroll 4
    for (int jj = WHALF + G - 1; jj < jhi; jj++) {
        const size_t off = (size_t)(i0 + jj - WHALF) * DIM + d;
        const float t1 = T1p[off], t2 = T2[off];
        AGGH(csAp, csB, 0, t1, t2);
        AGGH(csAp, csB, 8, t1, t2);
    }

    // ---- log_softmax over D ----
    float* const s_acc = reinterpret_cast<float*>(sm + OFF_SACC);
    __syncthreads();
#pragma unroll
    for (int li = 0; li < G; li++) s_acc[li * DIM + d] = acc[li];
    __syncthreads();
#pragma unroll
    for (int rr = 0; rr < 2; rr++) {
        const int r = wi + rr * 8;
        float v[8];
#pragma unroll
        for (int k = 0; k < 8; k++) v[k] = s_acc[r * DIM + lane + 32 * k];
        float m = v[0];
#pragma unroll
        for (int k = 1; k < 8; k++) m = fmaxf(m, v[k]);
        m = warpMax(m);
        float s = 0.f;
#pragma unroll
        for (int k = 0; k < 8; k++) s += __expf(v[k] - m);
        s = warpSum(s);
        if (lane == 0) slse[r] = m + logf(s);
    }
    __syncthreads();
#pragma unroll
    for (int li = 0; li < G; li++)
        out[(size_t)(i0 + li) * DIM + d] = acc[li] - slse[li];
}

// ---------------------------------------------------------------------------
extern "C" void kernel_launch(void* const* d_in, const int* in_sizes, int n_in,
                              void* d_out, int out_size) {
    const float* x   = (const float*)d_in[0];
    const int*   spk = (const int*)d_in[1];
    const float* Wa  = (const float*)d_in[2];
    const float* Wp  = (const float*)d_in[3];
    const float* Ws  = (const float*)d_in[4];
    const float* Wm  = (const float*)d_in[5];
    const float* Wd  = (const float*)d_in[6];
    float* out = (float*)d_out;

    cudaFuncSetAttribute(gemm_tc_kernel, cudaFuncAttributeMaxDynamicSharedMemorySize, GSM_TOTAL);
    cudaFuncSetAttribute(fused_kernel, cudaFuncAttributeMaxDynamicSharedMemorySize, SMF_TOTAL);

    split_x_kernel<<<N_UTT * DIM / 2048, 256>>>(x);
    prep_w_kernel<<<DIM * DIM / 256, 256>>>(Wa, Wp, Ws, Wm, Wd);
    gemm_tc_kernel<<<dim3(N_UTT / 128, 8), 256, GSM_TOTAL>>>();
    fused_kernel<<<N_UTT / G, 256, SMF_TOTAL>>>(spk, out);
}

// round 15
// speedup vs baseline: 1.1142x; 1.1032x over previous
#include <cuda_runtime.h>
#include <cuda_bf16.h>
#include <cstdint>

#define N_UTT 16384
#define DIM   256
#define WHALF 64
#define WIN   128
#define G     16
#define NW    143            // WIN + G - 1
#define NPAD  144

// Scratch: [0]=Q=x@W_att, [1]=T1p=x@Wc1, [2]=T1s=x@Wc2, [3]=T2=x@Wc3
__device__ float g_scratch[4ULL * N_UTT * DIM];
__device__ __align__(16) unsigned short g_xhi[N_UTT * DIM];
__device__ __align__(16) unsigned short g_xlo[N_UTT * DIM];
__device__ __align__(16) unsigned short g_wthi[4 * DIM * DIM];
__device__ __align__(16) unsigned short g_wtlo[4 * DIM * DIM];

__device__ __forceinline__ uint32_t smem_to_u32(const void* p) {
    uint32_t a;
    asm("{ .reg .u64 t; cvta.to.shared.u64 t, %1; cvt.u32.u64 %0, t; }" : "=r"(a) : "l"(p));
    return a;
}
__device__ __forceinline__ void ldsm_x4(uint32_t* r, uint32_t addr) {
    asm volatile("ldmatrix.sync.aligned.m8n8.x4.shared.b16 {%0,%1,%2,%3}, [%4];"
                 : "=r"(r[0]), "=r"(r[1]), "=r"(r[2]), "=r"(r[3]) : "r"(addr));
}
__device__ __forceinline__ void mma16816(float* c, const uint32_t* a, const uint32_t* b) {
    asm volatile(
        "mma.sync.aligned.m16n8k16.row.col.f32.bf16.bf16.f32 "
        "{%0,%1,%2,%3}, {%4,%5,%6,%7}, {%8,%9}, {%0,%1,%2,%3};"
        : "+f"(c[0]), "+f"(c[1]), "+f"(c[2]), "+f"(c[3])
        : "r"(a[0]), "r"(a[1]), "r"(a[2]), "r"(a[3]), "r"(b[0]), "r"(b[1]));
}
__device__ __forceinline__ void cp_async16(uint32_t dst, const void* src) {
    asm volatile("cp.async.ca.shared.global [%0], [%1], 16;" :: "r"(dst), "l"(src));
}
#define CP_COMMIT()  asm volatile("cp.async.commit_group;" ::: "memory")
#define CP_WAIT(N)   asm volatile("cp.async.wait_group %0;" :: "n"(N) : "memory")

// ===========================================================================
// Prep kernels
// ===========================================================================
__device__ __forceinline__ void bf16_split(float v, unsigned short& hi, unsigned short& lo) {
    __nv_bfloat16 h = __float2bfloat16(v);
    float r = v - __bfloat162float(h);
    hi = __bfloat16_as_ushort(h);
    lo = __bfloat16_as_ushort(__float2bfloat16(r));
}

__global__ void split_x_kernel(const float* __restrict__ x) {
    const int i = (blockIdx.x * 256 + threadIdx.x) * 8;
    float4 v0 = *reinterpret_cast<const float4*>(x + i);
    float4 v1 = *reinterpret_cast<const float4*>(x + i + 4);
    ushort4 h0, l0, h1, l1;
    bf16_split(v0.x, h0.x, l0.x); bf16_split(v0.y, h0.y, l0.y);
    bf16_split(v0.z, h0.z, l0.z); bf16_split(v0.w, h0.w, l0.w);
    bf16_split(v1.x, h1.x, l1.x); bf16_split(v1.y, h1.y, l1.y);
    bf16_split(v1.z, h1.z, l1.z); bf16_split(v1.w, h1.w, l1.w);
    *reinterpret_cast<ushort4*>(g_xhi + i)     = h0;
    *reinterpret_cast<ushort4*>(g_xhi + i + 4) = h1;
    *reinterpret_cast<ushort4*>(g_xlo + i)     = l0;
    *reinterpret_cast<ushort4*>(g_xlo + i + 4) = l1;
}

__global__ void prep_w_kernel(const float* __restrict__ Wa, const float* __restrict__ Wp,
                              const float* __restrict__ Ws, const float* __restrict__ Wm,
                              const float* __restrict__ Wd) {
    const int idx = blockIdx.x * 256 + threadIdx.x;  // idx = k*256 + n
    const int k = idx >> 8, n = idx & 255;
    const float p = Wp[idx], s = Ws[idx], m = Wm[idx], d = Wd[idx], a = Wa[idx];
    const float avg = 0.5f * (m + d);
    float vals[4] = {a, p + avg, s + avg, m - d};
    const int tr = n * DIM + k;
#pragma unroll
    for (int w = 0; w < 4; w++) {
        unsigned short hi, lo;
        bf16_split(vals[w], hi, lo);
        g_wthi[w * DIM * DIM + tr] = hi;
        g_wtlo[w * DIM * DIM + tr] = lo;
    }
}

// ===========================================================================
// Warp-MMA bf16x3 GEMM, cp.async double-buffered, KC=32
// ===========================================================================
#define GKC     32
#define GSTR    40
#define GTILE   (128 * GSTR * 2)
#define OFF_GAH 0
#define OFF_GAL (GTILE)
#define OFF_GBH (2 * GTILE)
#define OFF_GBL (3 * GTILE)
#define GSTAGE  (4 * GTILE)
#define GSM_TOTAL (2 * GSTAGE)

__global__ void __launch_bounds__(256) gemm_tc_kernel() {
    extern __shared__ __align__(16) char smem[];
    const uint32_t sb = smem_to_u32(smem);
    const int tid  = threadIdx.x;
    const int wid  = tid >> 5;
    const int lane = tid & 31;

    const int row0  = blockIdx.x * 128;
    const int widx  = blockIdx.y >> 1;
    const int ncol0 = (blockIdx.y & 1) * 128;

    float* __restrict__ Cout = g_scratch + (size_t)widx * N_UTT * DIM;
    const unsigned short* __restrict__ wth = g_wthi + widx * DIM * DIM;
    const unsigned short* __restrict__ wtl = g_wtlo + widx * DIM * DIM;

    const int m0w = (wid & 1) * 64;
    const int n0w = (wid >> 1) * 32;

    float acc[4][4][4];
#pragma unroll
    for (int a = 0; a < 4; a++)
#pragma unroll
        for (int b = 0; b < 4; b++)
#pragma unroll
            for (int c = 0; c < 4; c++) acc[a][b][c] = 0.f;

    const uint32_t a_lane_off = (uint32_t)((m0w + (lane & 15)) * 80 + (lane >> 4) * 16);
    const uint32_t b_lane_off = (uint32_t)((n0w + (lane & 7) + ((lane >> 4) << 3)) * 80 + (lane & 8) * 2);

    const int r0s = tid >> 2, f0s = tid & 3;
    const int r1s = (tid + 256) >> 2, f1s = tid & 3;

#define GPREFETCH(CIDX, ST)                                                              \
    do {                                                                                 \
        const int _k0 = (CIDX) * GKC;                                                    \
        const uint32_t _sbase = sb + (ST) * GSTAGE;                                      \
        {                                                                                \
            const uint32_t _do = (uint32_t)(r0s * 80 + f0s * 16);                        \
            const size_t _sa = (size_t)(row0 + r0s) * DIM + _k0 + f0s * 8;               \
            const size_t _sbv = (size_t)(ncol0 + r0s) * DIM + _k0 + f0s * 8;             \
            cp_async16(_sbase + OFF_GAH + _do, g_xhi + _sa);                             \
            cp_async16(_sbase + OFF_GAL + _do, g_xlo + _sa);                             \
            cp_async16(_sbase + OFF_GBH + _do, wth + _sbv);                              \
            cp_async16(_sbase + OFF_GBL + _do, wtl + _sbv);                              \
        }                                                                                \
        {                                                                                \
            const uint32_t _do = (uint32_t)(r1s * 80 + f1s * 16);                        \
            const size_t _sa = (size_t)(row0 + r1s) * DIM + _k0 + f1s * 8;               \
            const size_t _sbv = (size_t)(ncol0 + r1s) * DIM + _k0 + f1s * 8;             \
            cp_async16(_sbase + OFF_GAH + _do, g_xhi + _sa);                             \
            cp_async16(_sbase + OFF_GAL + _do, g_xlo + _sa);                             \
            cp_async16(_sbase + OFF_GBH + _do, wth + _sbv);                              \
            cp_async16(_sbase + OFF_GBL + _do, wtl + _sbv);                              \
        }                                                                                \
    } while (0)

    GPREFETCH(0, 0); CP_COMMIT();
    GPREFETCH(1, 1); CP_COMMIT();
    CP_WAIT(1);
    __syncthreads();

    for (int c = 0; c < 8; c++) {
        const uint32_t sst = sb + (c & 1) * GSTAGE;
#pragma unroll
        for (int ks = 0; ks < 2; ks++) {
            const uint32_t kb = (uint32_t)(ks * 32);
            uint32_t bh[2][4], bl[2][4];
#pragma unroll
            for (int nt = 0; nt < 2; nt++) {
                ldsm_x4(bh[nt], sst + OFF_GBH + b_lane_off + (uint32_t)(nt * 16 * 80) + kb);
                ldsm_x4(bl[nt], sst + OFF_GBL + b_lane_off + (uint32_t)(nt * 16 * 80) + kb);
            }
#pragma unroll
            for (int mt = 0; mt < 4; mt++) {
                uint32_t ah[4], al[4];
                const uint32_t mto = (uint32_t)(mt * 16 * 80) + kb;
                ldsm_x4(ah, sst + OFF_GAH + a_lane_off + mto);
                ldsm_x4(al, sst + OFF_GAL + a_lane_off + mto);
#pragma unroll
                for (int n8 = 0; n8 < 4; n8++) {
                    mma16816(acc[mt][n8], ah, &bh[n8 >> 1][(n8 & 1) * 2]);
                    mma16816(acc[mt][n8], ah, &bl[n8 >> 1][(n8 & 1) * 2]);
                    mma16816(acc[mt][n8], al, &bh[n8 >> 1][(n8 & 1) * 2]);
                }
            }
        }
        __syncthreads();
        if (c + 2 < 8) { GPREFETCH(c + 2, c & 1); CP_COMMIT(); }
        if (c + 1 < 8) {
            if (c + 2 < 8) CP_WAIT(1);
            else           CP_WAIT(0);
            __syncthreads();
        }
    }

    const int qr = lane >> 2, qc = (lane & 3) * 2;
#pragma unroll
    for (int mt = 0; mt < 4; mt++) {
        const int row = row0 + m0w + mt * 16 + qr;
#pragma unroll
        for (int n8 = 0; n8 < 4; n8++) {
            const int col = ncol0 + n0w + n8 * 8 + qc;
            *reinterpret_cast<float2*>(&Cout[(size_t)row * DIM + col]) =
                make_float2(acc[mt][n8][0], acc[mt][n8][1]);
            *reinterpret_cast<float2*>(&Cout[(size_t)(row + 8) * DIM + col]) =
                make_float2(acc[mt][n8][2], acc[mt][n8][3]);
        }
    }
}

// ===========================================================================
// Fused (G=16): MMA band attention + softmax + aggregation + log_softmax
// Aggressive live-range aliasing: 44.5 KB smem -> 4 CTAs/SM
// ===========================================================================
#define KCF     32
#define AW_STR  40
#define Q_STR   264
#define LOG_STR 17

// Phase A (attention MMA): window + Q + persistent spkw/slse
#define OFF_AWH   0                       // 144*80  = 11520
#define OFF_AWL   11520                   // -> 23040
#define OFF_QH    23040                   // 16*528 = 8448
#define OFF_QL    31488                   // -> 39936
#define OFF_SLSE  43840                   // 64     -> 43904
#define OFF_SPKW  43904                   // 144*4  -> 44480
#define SMF_TOTAL 44480
// Aliases:
#define OFF_SLOG  0                       // 9792  (over AWH; window dead after c-loop)
#define OFF_SATTN 27456                   // 8192  (over QH/QL; Q dead after c-loop)
#define OFF_CSAP  0                       // 9152  (over slog; dead after softmax)
#define OFF_CSAS  9152
#define OFF_CSB   18304                   // -> 27456
#define OFF_SACC  27456                   // 16384 -> 43840 (over sattn; dead after coef build)

__device__ __forceinline__ float warpMax(float v) {
#pragma unroll
    for (int o = 16; o > 0; o >>= 1) v = fmaxf(v, __shfl_xor_sync(0xffffffffu, v, o));
    return v;
}
__device__ __forceinline__ float warpSum(float v) {
#pragma unroll
    for (int o = 16; o > 0; o >>= 1) v += __shfl_xor_sync(0xffffffffu, v, o);
    return v;
}

__global__ void __launch_bounds__(256, 4) fused_kernel(const int* __restrict__ spk,
                                                       float* __restrict__ out) {
    extern __shared__ __align__(16) char sm[];
    const uint32_t sb = smem_to_u32(sm);

    const int i0   = blockIdx.x * G;
    const int tid  = threadIdx.x;
    const int wi   = tid >> 5;
    const int lane = tid & 31;

    const float* __restrict__ Q   = g_scratch;
    const float* __restrict__ T1p = g_scratch + 1ULL * N_UTT * DIM;
    const float* __restrict__ T1s = g_scratch + 2ULL * N_UTT * DIM;
    const float* __restrict__ T2  = g_scratch + 3ULL * N_UTT * DIM;

    float* const slog  = reinterpret_cast<float*>(sm + OFF_SLOG);
    float* const sattn = reinterpret_cast<float*>(sm + OFF_SATTN);
    int*   const spkw  = reinterpret_cast<int*>(sm + OFF_SPKW);
    float* const slse  = reinterpret_cast<float*>(sm + OFF_SLSE);

    // ---- Q rows fp32 -> bf16 hi/lo in smem ----
    {
        const int row = tid >> 4;
        const int c0  = (tid & 15) * 16;
        const float* qs = Q + (size_t)(i0 + row) * DIM + c0;
#pragma unroll
        for (int h = 0; h < 2; h++) {
            float4 v0 = *reinterpret_cast<const float4*>(qs + 8 * h);
            float4 v1 = *reinterpret_cast<const float4*>(qs + 8 * h + 4);
            unsigned short hh[8], ll[8];
            bf16_split(v0.x, hh[0], ll[0]); bf16_split(v0.y, hh[1], ll[1]);
            bf16_split(v0.z, hh[2], ll[2]); bf16_split(v0.w, hh[3], ll[3]);
            bf16_split(v1.x, hh[4], ll[4]); bf16_split(v1.y, hh[5], ll[5]);
            bf16_split(v1.z, hh[6], ll[6]); bf16_split(v1.w, hh[7], ll[7]);
            *reinterpret_cast<uint4*>(sm + OFF_QH + row * (Q_STR * 2) + (c0 + 8 * h) * 2) =
                *reinterpret_cast<uint4*>(hh);
            *reinterpret_cast<uint4*>(sm + OFF_QL + row * (Q_STR * 2) + (c0 + 8 * h) * 2) =
                *reinterpret_cast<uint4*>(ll);
        }
    }
    if (tid < NW) {
        int j = i0 + tid - WHALF;
        j = min(max(j, 0), N_UTT - 1);
        spkw[tid] = spk[j];
    }

    // ---- band QK^T via m16n8k16 bf16x3; B tile n=16 ----
    float facc[2][2][4];
#pragma unroll
    for (int t = 0; t < 2; t++)
#pragma unroll
        for (int n8 = 0; n8 < 2; n8++)
#pragma unroll
            for (int k = 0; k < 4; k++) facc[t][n8][k] = 0.f;

    const uint32_t aoff = (uint32_t)(((lane & 15) * AW_STR + ((lane >> 4) << 3)) * 2);
    const uint32_t boff = (uint32_t)((((lane & 7) + ((lane >> 4) << 3)) * Q_STR + (lane & 8)) * 2);

    for (int c = 0; c < 8; c++) {
        __syncthreads();
        for (int s = tid; s < 576; s += 256) {
            const int r = s >> 2, f = s & 3;
            const int j = i0 + r - WHALF;
            uint4 vh = make_uint4(0, 0, 0, 0), vl = make_uint4(0, 0, 0, 0);
            if (r < NW && j >= 0 && j < N_UTT) {
                const size_t src = (size_t)j * DIM + c * KCF + f * 8;
                vh = *reinterpret_cast<const uint4*>(g_xhi + src);
                vl = *reinterpret_cast<const uint4*>(g_xlo + src);
            }
            *reinterpret_cast<uint4*>(sm + OFF_AWH + r * (AW_STR * 2) + f * 16) = vh;
            *reinterpret_cast<uint4*>(sm + OFF_AWL + r * (AW_STR * 2) + f * 16) = vl;
        }
        __syncthreads();
#pragma unroll
        for (int ks = 0; ks < 2; ks++) {
            uint32_t bh[4], bl[4];
            const uint32_t kqb = (uint32_t)(c * KCF + ks * 16) * 2;
            ldsm_x4(bh, sb + OFF_QH + boff + kqb);
            ldsm_x4(bl, sb + OFF_QL + boff + kqb);
            int ti = 0;
            for (int mt = wi; mt < 9; mt += 8, ti++) {
                uint32_t ah[4], al[4];
                const uint32_t mtoff = (uint32_t)(mt * 16 * AW_STR * 2) + (uint32_t)(ks * 32);
                ldsm_x4(ah, sb + OFF_AWH + mtoff + aoff);
                ldsm_x4(al, sb + OFF_AWL + mtoff + aoff);
#pragma unroll
                for (int n8 = 0; n8 < 2; n8++) {
                    mma16816(facc[ti][n8], ah, &bh[n8 * 2]);
                    mma16816(facc[ti][n8], ah, &bl[n8 * 2]);
                    mma16816(facc[ti][n8], al, &bh[n8 * 2]);
                }
            }
        }
    }
    __syncthreads();   // all MMA window reads done before slog overwrites AWH
    {
        const int qr = lane >> 2, qc = (lane & 3) * 2;
        int ti = 0;
        for (int mt = wi; mt < 9; mt += 8, ti++) {
            const int r = mt * 16 + qr;
#pragma unroll
            for (int n8 = 0; n8 < 2; n8++) {
                const int col = n8 * 8 + qc;
                slog[r * LOG_STR + col]           = facc[ti][n8][0];
                slog[r * LOG_STR + col + 1]       = facc[ti][n8][1];
                slog[(r + 8) * LOG_STR + col]     = facc[ti][n8][2];
                slog[(r + 8) * LOG_STR + col + 1] = facc[ti][n8][3];
            }
        }
    }
    __syncthreads();

    // ---- softmax: warp wi owns rows wi and wi+8 (sattn over dead Q) ----
#pragma unroll
    for (int rr = 0; rr < 2; rr++) {
        const int li = wi + rr * 8;
        const int i  = i0 + li;
        float v0 = slog[(li + lane) * LOG_STR + li];
        float v1 = slog[(li + lane + 32) * LOG_STR + li];
        float v2 = slog[(li + lane + 64) * LOG_STR + li];
        float v3 = slog[(li + lane + 96) * LOG_STR + li];
        float m = warpMax(fmaxf(fmaxf(v0, v1), fmaxf(v2, v3)));
        const float e0 = __expf(v0 - m), e1 = __expf(v1 - m),
                    e2 = __expf(v2 - m), e3 = __expf(v3 - m);
        const float inv = 1.f / warpSum(e0 + e1 + e2 + e3);
        int j;
        j = i + lane - WHALF;       sattn[li * WIN + lane]      = (j >= 0 && j < N_UTT) ? e0 * inv : 0.f;
        j = i + lane - WHALF + 32;  sattn[li * WIN + lane + 32] = (j >= 0 && j < N_UTT) ? e1 * inv : 0.f;
        j = i + lane - WHALF + 64;  sattn[li * WIN + lane + 64] = (j >= 0 && j < N_UTT) ? e2 * inv : 0.f;
        j = i + lane - WHALF + 96;  sattn[li * WIN + lane + 96] = (j >= 0 && j < N_UTT) ? e3 * inv : 0.f;
    }
    __syncthreads();

    // ---- coefficient tables [jj][li=16] (over dead slog/window) ----
    float* const csAp = reinterpret_cast<float*>(sm + OFF_CSAP);
    float* const csAs = reinterpret_cast<float*>(sm + OFF_CSAS);
    float* const csB  = reinterpret_cast<float*>(sm + OFF_CSB);
    for (int t = tid; t < NW * G; t += 256) {
        const int jj = t >> 4, li = t & 15;
        const int w = jj - li;
        const float c = (w >= 0 && w < WIN) ? sattn[li * WIN + w] : 0.f;
        csAp[t] = (w >= WHALF) ? c : 0.f;
        csAs[t] = (w < WHALF) ? c : 0.f;
        csB[t]  = (spkw[jj] == spkw[WHALF + li]) ? 0.5f * c : -0.5f * c;
    }
    __syncthreads();

    // ---- aggregation ----
    const int d = tid;
    float acc[G];
#pragma unroll
    for (int li = 0; li < G; li++) acc[li] = 0.f;

    const int jlo = (i0 < WHALF) ? (WHALF - i0) : 0;
    const int jhi = min(NW, N_UTT - i0 + WHALF);

#define AGGH(AV, BV, HB, T1V, T2V)                                                   \
    do {                                                                             \
        const float4 a0 = *reinterpret_cast<const float4*>(&(AV)[jj * 16 + (HB)]);   \
        const float4 a1 = *reinterpret_cast<const float4*>(&(AV)[jj * 16 + (HB) + 4]);\
        const float4 b0 = *reinterpret_cast<const float4*>(&(BV)[jj * 16 + (HB)]);   \
        const float4 b1 = *reinterpret_cast<const float4*>(&(BV)[jj * 16 + (HB) + 4]);\
        acc[(HB) + 0] = fmaf(a0.x, (T1V), fmaf(b0.x, (T2V), acc[(HB) + 0]));         \
        acc[(HB) + 1] = fmaf(a0.y, (T1V), fmaf(b0.y, (T2V), acc[(HB) + 1]));         \
        acc[(HB) + 2] = fmaf(a0.z, (T1V), fmaf(b0.z, (T2V), acc[(HB) + 2]));         \
        acc[(HB) + 3] = fmaf(a0.w, (T1V), fmaf(b0.w, (T2V), acc[(HB) + 3]));         \
        acc[(HB) + 4] = fmaf(a1.x, (T1V), fmaf(b1.x, (T2V), acc[(HB) + 4]));         \
        acc[(HB) + 5] = fmaf(a1.y, (T1V), fmaf(b1.y, (T2V), acc[(HB) + 5]));         \
        acc[(HB) + 6] = fmaf(a1.z, (T1V), fmaf(b1.z, (T2V), acc[(HB) + 6]));         \
        acc[(HB) + 7] = fmaf(a1.w, (T1V), fmaf(b1.w, (T2V), acc[(HB) + 7]));         \
    } while (0)

#pragma unroll 4
    for (int jj = jlo; jj < WHALF; jj++) {
        const size_t off = (size_t)(i0 + jj - WHALF) * DIM + d;
        const float t1 = T1s[off], t2 = T2[off];
        AGGH(csAs, csB, 0, t1, t2);
        AGGH(csAs, csB, 8, t1, t2);
    }
    for (int jj = WHALF; jj < WHALF + G - 1; jj++) {
        const size_t off = (size_t)(i0 + jj - WHALF) * DIM + d;
        const float t1p = T1p[off], t1s = T1s[off], t2 = T2[off];
#pragma unroll
        for (int hb = 0; hb < 16; hb += 8) {
            const float4 p0 = *reinterpret_cast<const float4*>(&csAp[jj * 16 + hb]);
            const float4 p1 = *reinterpret_cast<const float4*>(&csAp[jj * 16 + hb + 4]);
            const float4 s0 = *reinterpret_cast<const float4*>(&csAs[jj * 16 + hb]);
            const float4 s1 = *reinterpret_cast<const float4*>(&csAs[jj * 16 + hb + 4]);
            const float4 b0 = *reinterpret_cast<const float4*>(&csB[jj * 16 + hb]);
            const float4 b1 = *reinterpret_cast<const float4*>(&csB[jj * 16 + hb + 4]);
            acc[hb + 0] = fmaf(p0.x, t1p, fmaf(s0.x, t1s, fmaf(b0.x, t2, acc[hb + 0])));
            acc[hb + 1] = fmaf(p0.y, t1p, fmaf(s0.y, t1s, fmaf(b0.y, t2, acc[hb + 1])));
            acc[hb + 2] = fmaf(p0.z, t1p, fmaf(s0.z, t1s, fmaf(b0.z, t2, acc[hb + 2])));
            acc[hb + 3] = fmaf(p0.w, t1p, fmaf(s0.w, t1s, fmaf(b0.w, t2, acc[hb + 3])));
            acc[hb + 4] = fmaf(p1.x, t1p, fmaf(s1.x, t1s, fmaf(b1.x, t2, acc[hb + 4])));
            acc[hb + 5] = fmaf(p1.y, t1p, fmaf(s1.y, t1s, fmaf(b1.y, t2, acc[hb + 5])));
            acc[hb + 6] = fmaf(p1.z, t1p, fmaf(s1.z, t1s, fmaf(b1.z, t2, acc[hb + 6])));
            acc[hb + 7] = fmaf(p1.w, t1p, fmaf(s1.w, t1s, fmaf(b1.w, t2, acc[hb + 7])));
        }
    }
#pragma unroll 4
    for (int jj = WHALF + G - 1; jj < jhi; jj++) {
        const size_t off = (size_t)(i0 + jj - WHALF) * DIM + d;
        const float t1 = T1p[off], t2 = T2[off];
        AGGH(csAp, csB, 0, t1, t2);
        AGGH(csAp, csB, 8, t1, t2);
    }

    // ---- log_softmax over D (s_acc over dead sattn) ----
    float* const s_acc = reinterpret_cast<float*>(sm + OFF_SACC);
    __syncthreads();
#pragma unroll
    for (int li = 0; li < G; li++) s_acc[li * DIM + d] = acc[li];
    __syncthreads();
#pragma unroll
    for (int rr = 0; rr < 2; rr++) {
        const int r = wi + rr * 8;
        float v[8];
#pragma unroll
        for (int k = 0; k < 8; k++) v[k] = s_acc[r * DIM + lane + 32 * k];
        float m = v[0];
#pragma unroll
        for (int k = 1; k < 8; k++) m = fmaxf(m, v[k]);
        m = warpMax(m);
        float s = 0.f;
#pragma unroll
        for (int k = 0; k < 8; k++) s += __expf(v[k] - m);
        s = warpSum(s);
        if (lane == 0) slse[r] = m + logf(s);
    }
    __syncthreads();
#pragma unroll
    for (int li = 0; li < G; li++)
        out[(size_t)(i0 + li) * DIM + d] = acc[li] - slse[li];
}

// ---------------------------------------------------------------------------
extern "C" void kernel_launch(void* const* d_in, const int* in_sizes, int n_in,
                              void* d_out, int out_size) {
    const float* x   = (const float*)d_in[0];
    const int*   spk = (const int*)d_in[1];
    const float* Wa  = (const float*)d_in[2];
    const float* Wp  = (const float*)d_in[3];
    const float* Ws  = (const float*)d_in[4];
    const float* Wm  = (const float*)d_in[5];
    const float* Wd  = (const float*)d_in[6];
    float* out = (float*)d_out;

    cudaFuncSetAttribute(gemm_tc_kernel, cudaFuncAttributeMaxDynamicSharedMemorySize, GSM_TOTAL);
    cudaFuncSetAttribute(fused_kernel, cudaFuncAttributeMaxDynamicSharedMemorySize, SMF_TOTAL);

    split_x_kernel<<<N_UTT * DIM / 2048, 256>>>(x);
    prep_w_kernel<<<DIM * DIM / 256, 256>>>(Wa, Wp, Ws, Wm, Wd);
    gemm_tc_kernel<<<dim3(N_UTT / 128, 8), 256, GSM_TOTAL>>>();
    fused_kernel<<<N_UTT / G, 256, SMF_TOTAL>>>(spk, out);
}

// round 17
// speedup vs baseline: 1.1348x; 1.0184x over previous
#include <cuda_runtime.h>
#include <cuda_bf16.h>
#include <cstdint>

#define N_UTT 16384
#define DIM   256
#define WHALF 64
#define WIN   128
#define G     16
#define NW    143            // WIN + G - 1
#define NPAD  144

// Scratch: [0]=Q=x@W_att, [1]=T1p=x@Wc1, [2]=T1s=x@Wc2, [3]=T2=x@Wc3
__device__ float g_scratch[4ULL * N_UTT * DIM];
// combined+transposed weights, bf16 split: [widx][n][k]
__device__ __align__(16) unsigned short g_wthi[4 * DIM * DIM];
__device__ __align__(16) unsigned short g_wtlo[4 * DIM * DIM];

__device__ __forceinline__ uint32_t smem_to_u32(const void* p) {
    uint32_t a;
    asm("{ .reg .u64 t; cvta.to.shared.u64 t, %1; cvt.u32.u64 %0, t; }" : "=r"(a) : "l"(p));
    return a;
}
__device__ __forceinline__ void ldsm_x4(uint32_t* r, uint32_t addr) {
    asm volatile("ldmatrix.sync.aligned.m8n8.x4.shared.b16 {%0,%1,%2,%3}, [%4];"
                 : "=r"(r[0]), "=r"(r[1]), "=r"(r[2]), "=r"(r[3]) : "r"(addr));
}
__device__ __forceinline__ void mma16816(float* c, const uint32_t* a, const uint32_t* b) {
    asm volatile(
        "mma.sync.aligned.m16n8k16.row.col.f32.bf16.bf16.f32 "
        "{%0,%1,%2,%3}, {%4,%5,%6,%7}, {%8,%9}, {%0,%1,%2,%3};"
        : "+f"(c[0]), "+f"(c[1]), "+f"(c[2]), "+f"(c[3])
        : "r"(a[0]), "r"(a[1]), "r"(a[2]), "r"(a[3]), "r"(b[0]), "r"(b[1]));
}
__device__ __forceinline__ void cp_async16(uint32_t dst, const void* src) {
    asm volatile("cp.async.ca.shared.global [%0], [%1], 16;" :: "r"(dst), "l"(src));
}
#define CP_COMMIT()  asm volatile("cp.async.commit_group;" ::: "memory")
#define CP_WAIT(N)   asm volatile("cp.async.wait_group %0;" :: "n"(N) : "memory")

__device__ __forceinline__ void bf16_split(float v, unsigned short& hi, unsigned short& lo) {
    __nv_bfloat16 h = __float2bfloat16(v);
    float r = v - __bfloat162float(h);
    hi = __bfloat16_as_ushort(h);
    lo = __bfloat16_as_ushort(__float2bfloat16(r));
}
// 8 fp32 -> uint4 hi + uint4 lo (16 bf16 each)
__device__ __forceinline__ void split8(const float4 v0, const float4 v1, uint4& uh, uint4& ul) {
    unsigned short hh[8], ll[8];
    bf16_split(v0.x, hh[0], ll[0]); bf16_split(v0.y, hh[1], ll[1]);
    bf16_split(v0.z, hh[2], ll[2]); bf16_split(v0.w, hh[3], ll[3]);
    bf16_split(v1.x, hh[4], ll[4]); bf16_split(v1.y, hh[5], ll[5]);
    bf16_split(v1.z, hh[6], ll[6]); bf16_split(v1.w, hh[7], ll[7]);
    uh = *reinterpret_cast<uint4*>(hh);
    ul = *reinterpret_cast<uint4*>(ll);
}

// ===========================================================================
// prep_w: combine + transpose + split weights
// ===========================================================================
__global__ void prep_w_kernel(const float* __restrict__ Wa, const float* __restrict__ Wp,
                              const float* __restrict__ Ws, const float* __restrict__ Wm,
                              const float* __restrict__ Wd) {
    const int idx = blockIdx.x * 256 + threadIdx.x;  // idx = k*256 + n
    const int k = idx >> 8, n = idx & 255;
    const float p = Wp[idx], s = Ws[idx], m = Wm[idx], d = Wd[idx], a = Wa[idx];
    const float avg = 0.5f * (m + d);
    float vals[4] = {a, p + avg, s + avg, m - d};
    const int tr = n * DIM + k;
#pragma unroll
    for (int w = 0; w < 4; w++) {
        unsigned short hi, lo;
        bf16_split(vals[w], hi, lo);
        g_wthi[w * DIM * DIM + tr] = hi;
        g_wtlo[w * DIM * DIM + tr] = lo;
    }
}

// ===========================================================================
// Warp-MMA bf16x3 GEMM: A from fp32 x (reg double-buffer + in-kernel split),
// B cp.async double-buffered, 1 sync per chunk. KC=32.
// ===========================================================================
#define GKC     32
#define GTILE   (128 * 40 * 2)        // 10240 B per bf16 tile (80B rows)
#define OFF_GAH 0
#define OFF_GAL (GTILE)
#define OFF_GBH (2 * GTILE)
#define OFF_GBL (3 * GTILE)
#define GSTAGE  (4 * GTILE)           // 40960
#define GSM_TOTAL (2 * GSTAGE)        // 81920

__global__ void __launch_bounds__(256, 2) gemm_tc_kernel(const float* __restrict__ x) {
    extern __shared__ __align__(16) char smem[];
    const uint32_t sb = smem_to_u32(smem);
    const int tid  = threadIdx.x;
    const int wid  = tid >> 5;
    const int lane = tid & 31;

    const int row0  = blockIdx.x * 128;
    const int widx  = blockIdx.y >> 1;
    const int ncol0 = (blockIdx.y & 1) * 128;

    float* __restrict__ Cout = g_scratch + (size_t)widx * N_UTT * DIM;
    const unsigned short* __restrict__ wth = g_wthi + widx * DIM * DIM;
    const unsigned short* __restrict__ wtl = g_wtlo + widx * DIM * DIM;

    const int m0w = (wid & 1) * 64;
    const int n0w = (wid >> 1) * 32;

    float acc[4][4][4];
#pragma unroll
    for (int a = 0; a < 4; a++)
#pragma unroll
        for (int b = 0; b < 4; b++)
#pragma unroll
            for (int c = 0; c < 4; c++) acc[a][b][c] = 0.f;

    const uint32_t a_lane_off = (uint32_t)((m0w + (lane & 15)) * 80 + (lane >> 4) * 16);
    const uint32_t b_lane_off = (uint32_t)((n0w + (lane & 7) + ((lane >> 4) << 3)) * 80 + (lane & 8) * 2);

    // A mapping: thread owns row rA, k-half kb (16 elems)
    const int rA = tid >> 1;
    const int kb = (tid & 1) * 16;
    const float* __restrict__ xrow = x + (size_t)(row0 + rA) * DIM + kb;
    const uint32_t a_sts = (uint32_t)(rA * 80 + kb * 2);   // byte offset in tile

    // B mapping: 2 (r,f) pairs per thread per buffer
    const int rB0 = tid >> 1;
    const int fB0 = (tid & 1) * 2;

#define GB_ISSUE(CIDX, ST)                                                             \
    do {                                                                               \
        const int _k0 = (CIDX) * GKC;                                                  \
        const uint32_t _sbase = sb + (ST) * GSTAGE;                                    \
        _Pragma("unroll")                                                              \
        for (int _q = 0; _q < 2; _q++) {                                               \
            const int _f = fB0 + _q;                                                   \
            const uint32_t _do = (uint32_t)(rB0 * 80 + _f * 16);                       \
            const size_t _s = (size_t)(ncol0 + rB0) * DIM + _k0 + _f * 8;              \
            cp_async16(_sbase + OFF_GBH + _do, wth + _s);                              \
            cp_async16(_sbase + OFF_GBL + _do, wtl + _s);                              \
        }                                                                              \
    } while (0)

#define GA_LDG(CIDX, AV)                                                               \
    do {                                                                               \
        const float* _p = xrow + (CIDX) * GKC;                                         \
        (AV)[0] = *reinterpret_cast<const float4*>(_p);                                \
        (AV)[1] = *reinterpret_cast<const float4*>(_p + 4);                            \
        (AV)[2] = *reinterpret_cast<const float4*>(_p + 8);                            \
        (AV)[3] = *reinterpret_cast<const float4*>(_p + 12);                           \
    } while (0)

#define GA_STS(AV, ST)                                                                 \
    do {                                                                               \
        uint4 _h0, _l0, _h1, _l1;                                                      \
        split8((AV)[0], (AV)[1], _h0, _l0);                                            \
        split8((AV)[2], (AV)[3], _h1, _l1);                                            \
        char* _smc = smem + (ST) * GSTAGE;                                             \
        *reinterpret_cast<uint4*>(_smc + OFF_GAH + a_sts)      = _h0;                  \
        *reinterpret_cast<uint4*>(_smc + OFF_GAH + a_sts + 16) = _h1;                  \
        *reinterpret_cast<uint4*>(_smc + OFF_GAL + a_sts)      = _l0;                  \
        *reinterpret_cast<uint4*>(_smc + OFF_GAL + a_sts + 16) = _l1;                  \
    } while (0)

    // prologue: B0 + A0 into stage 0
    GB_ISSUE(0, 0); CP_COMMIT();
    {
        float4 av[4];
        GA_LDG(0, av);
        GA_STS(av, 0);
    }
    CP_WAIT(0);
    __syncthreads();

    for (int c = 0; c < 8; c++) {
        const int nxt = (c + 1) & 1;
        if (c + 1 < 8) { GB_ISSUE(c + 1, nxt); CP_COMMIT(); }
        float4 av[4];
        if (c + 1 < 8) GA_LDG(c + 1, av);

        const uint32_t sst = sb + (c & 1) * GSTAGE;
#pragma unroll
        for (int ks = 0; ks < 2; ks++) {
            const uint32_t kbb = (uint32_t)(ks * 32);
            uint32_t bh[2][4], bl[2][4];
#pragma unroll
            for (int nt = 0; nt < 2; nt++) {
                ldsm_x4(bh[nt], sst + OFF_GBH + b_lane_off + (uint32_t)(nt * 16 * 80) + kbb);
                ldsm_x4(bl[nt], sst + OFF_GBL + b_lane_off + (uint32_t)(nt * 16 * 80) + kbb);
            }
#pragma unroll
            for (int mt = 0; mt < 4; mt++) {
                uint32_t ah[4], al[4];
                const uint32_t mto = (uint32_t)(mt * 16 * 80) + kbb;
                ldsm_x4(ah, sst + OFF_GAH + a_lane_off + mto);
                ldsm_x4(al, sst + OFF_GAL + a_lane_off + mto);
#pragma unroll
                for (int n8 = 0; n8 < 4; n8++) {
                    mma16816(acc[mt][n8], ah, &bh[n8 >> 1][(n8 & 1) * 2]);
                    mma16816(acc[mt][n8], ah, &bl[n8 >> 1][(n8 & 1) * 2]);
                    mma16816(acc[mt][n8], al, &bh[n8 >> 1][(n8 & 1) * 2]);
                }
            }
        }
        if (c + 1 < 8) {
            GA_STS(av, nxt);   // stage nxt's A readers finished at prev sync
            CP_WAIT(0);        // B(c+1) landed
        }
        __syncthreads();
    }

    const int qr = lane >> 2, qc = (lane & 3) * 2;
#pragma unroll
    for (int mt = 0; mt < 4; mt++) {
        const int row = row0 + m0w + mt * 16 + qr;
#pragma unroll
        for (int n8 = 0; n8 < 4; n8++) {
            const int col = ncol0 + n0w + n8 * 8 + qc;
            *reinterpret_cast<float2*>(&Cout[(size_t)row * DIM + col]) =
                make_float2(acc[mt][n8][0], acc[mt][n8][1]);
            *reinterpret_cast<float2*>(&Cout[(size_t)(row + 8) * DIM + col]) =
                make_float2(acc[mt][n8][2], acc[mt][n8][3]);
        }
    }
}

// ===========================================================================
// Fused (G=16): MMA band attention + softmax + aggregation + log_softmax
// Window staged from fp32 x with in-staging bf16 split. 44.5 KB smem.
// ===========================================================================
#define KCF     32
#define AW_STR  40
#define Q_STR   264
#define LOG_STR 17

#define OFF_AWH   0                       // 144*80  = 11520
#define OFF_AWL   11520                   // -> 23040
#define OFF_QH    23040                   // 16*528 = 8448
#define OFF_QL    31488                   // -> 39936
#define OFF_SLSE  43840
#define OFF_SPKW  43904
#define SMF_TOTAL 44480
// Aliases:
#define OFF_SLOG  0
#define OFF_SATTN 27456
#define OFF_CSAP  0
#define OFF_CSAS  9152
#define OFF_CSB   18304
#define OFF_SACC  27456

__device__ __forceinline__ float warpMax(float v) {
#pragma unroll
    for (int o = 16; o > 0; o >>= 1) v = fmaxf(v, __shfl_xor_sync(0xffffffffu, v, o));
    return v;
}
__device__ __forceinline__ float warpSum(float v) {
#pragma unroll
    for (int o = 16; o > 0; o >>= 1) v += __shfl_xor_sync(0xffffffffu, v, o);
    return v;
}

__global__ void __launch_bounds__(256, 4) fused_kernel(const float* __restrict__ x,
                                                       const int* __restrict__ spk,
                                                       float* __restrict__ out) {
    extern __shared__ __align__(16) char sm[];
    const uint32_t sb = smem_to_u32(sm);

    const int i0   = blockIdx.x * G;
    const int tid  = threadIdx.x;
    const int wi   = tid >> 5;
    const int lane = tid & 31;

    const float* __restrict__ Q   = g_scratch;
    const float* __restrict__ T1p = g_scratch + 1ULL * N_UTT * DIM;
    const float* __restrict__ T1s = g_scratch + 2ULL * N_UTT * DIM;
    const float* __restrict__ T2  = g_scratch + 3ULL * N_UTT * DIM;

    float* const slog  = reinterpret_cast<float*>(sm + OFF_SLOG);
    float* const sattn = reinterpret_cast<float*>(sm + OFF_SATTN);
    int*   const spkw  = reinterpret_cast<int*>(sm + OFF_SPKW);
    float* const slse  = reinterpret_cast<float*>(sm + OFF_SLSE);

    // ---- Q rows fp32 -> bf16 hi/lo in smem ----
    {
        const int row = tid >> 4;
        const int c0  = (tid & 15) * 16;
        const float* qs = Q + (size_t)(i0 + row) * DIM + c0;
#pragma unroll
        for (int h = 0; h < 2; h++) {
            float4 v0 = *reinterpret_cast<const float4*>(qs + 8 * h);
            float4 v1 = *reinterpret_cast<const float4*>(qs + 8 * h + 4);
            uint4 uh, ul;
            split8(v0, v1, uh, ul);
            *reinterpret_cast<uint4*>(sm + OFF_QH + row * (Q_STR * 2) + (c0 + 8 * h) * 2) = uh;
            *reinterpret_cast<uint4*>(sm + OFF_QL + row * (Q_STR * 2) + (c0 + 8 * h) * 2) = ul;
        }
    }
    if (tid < NW) {
        int j = i0 + tid - WHALF;
        j = min(max(j, 0), N_UTT - 1);
        spkw[tid] = spk[j];
    }

    // ---- band QK^T via m16n8k16 bf16x3; B tile n=16 ----
    float facc[2][2][4];
#pragma unroll
    for (int t = 0; t < 2; t++)
#pragma unroll
        for (int n8 = 0; n8 < 2; n8++)
#pragma unroll
            for (int k = 0; k < 4; k++) facc[t][n8][k] = 0.f;

    const uint32_t aoff = (uint32_t)(((lane & 15) * AW_STR + ((lane >> 4) << 3)) * 2);
    const uint32_t boff = (uint32_t)((((lane & 7) + ((lane >> 4) << 3)) * Q_STR + (lane & 8)) * 2);

    for (int c = 0; c < 8; c++) {
        __syncthreads();
        for (int s = tid; s < 576; s += 256) {
            const int r = s >> 2, f = s & 3;
            const int j = i0 + r - WHALF;
            uint4 uh = make_uint4(0, 0, 0, 0), ul = make_uint4(0, 0, 0, 0);
            if (r < NW && j >= 0 && j < N_UTT) {
                const float* xs = x + (size_t)j * DIM + c * KCF + f * 8;
                float4 v0 = *reinterpret_cast<const float4*>(xs);
                float4 v1 = *reinterpret_cast<const float4*>(xs + 4);
                split8(v0, v1, uh, ul);
            }
            *reinterpret_cast<uint4*>(sm + OFF_AWH + r * (AW_STR * 2) + f * 16) = uh;
            *reinterpret_cast<uint4*>(sm + OFF_AWL + r * (AW_STR * 2) + f * 16) = ul;
        }
        __syncthreads();
#pragma unroll
        for (int ks = 0; ks < 2; ks++) {
            uint32_t bh[4], bl[4];
            const uint32_t kqb = (uint32_t)(c * KCF + ks * 16) * 2;
            ldsm_x4(bh, sb + OFF_QH + boff + kqb);
            ldsm_x4(bl, sb + OFF_QL + boff + kqb);
            int ti = 0;
            for (int mt = wi; mt < 9; mt += 8, ti++) {
                uint32_t ah[4], al[4];
                const uint32_t mtoff = (uint32_t)(mt * 16 * AW_STR * 2) + (uint32_t)(ks * 32);
                ldsm_x4(ah, sb + OFF_AWH + mtoff + aoff);
                ldsm_x4(al, sb + OFF_AWL + mtoff + aoff);
#pragma unroll
                for (int n8 = 0; n8 < 2; n8++) {
                    mma16816(facc[ti][n8], ah, &bh[n8 * 2]);
                    mma16816(facc[ti][n8], ah, &bl[n8 * 2]);
                    mma16816(facc[ti][n8], al, &bh[n8 * 2]);
                }
            }
        }
    }
    __syncthreads();   // all MMA window reads done before slog overwrites AWH
    {
        const int qr = lane >> 2, qc = (lane & 3) * 2;
        int ti = 0;
        for (int mt = wi; mt < 9; mt += 8, ti++) {
            const int r = mt * 16 + qr;
#pragma unroll
            for (int n8 = 0; n8 < 2; n8++) {
                const int col = n8 * 8 + qc;
                slog[r * LOG_STR + col]           = facc[ti][n8][0];
                slog[r * LOG_STR + col + 1]       = facc[ti][n8][1];
                slog[(r + 8) * LOG_STR + col]     = facc[ti][n8][2];
                slog[(r + 8) * LOG_STR + col + 1] = facc[ti][n8][3];
            }
        }
    }
    __syncthreads();

    // ---- softmax: warp wi owns rows wi and wi+8 ----
#pragma unroll
    for (int rr = 0; rr < 2; rr++) {
        const int li = wi + rr * 8;
        const int i  = i0 + li;
        float v0 = slog[(li + lane) * LOG_STR + li];
        float v1 = slog[(li + lane + 32) * LOG_STR + li];
        float v2 = slog[(li + lane + 64) * LOG_STR + li];
        float v3 = slog[(li + lane + 96) * LOG_STR + li];
        float m = warpMax(fmaxf(fmaxf(v0, v1), fmaxf(v2, v3)));
        const float e0 = __expf(v0 - m), e1 = __expf(v1 - m),
                    e2 = __expf(v2 - m), e3 = __expf(v3 - m);
        const float inv = 1.f / warpSum(e0 + e1 + e2 + e3);
        int j;
        j = i + lane - WHALF;       sattn[li * WIN + lane]      = (j >= 0 && j < N_UTT) ? e0 * inv : 0.f;
        j = i + lane - WHALF + 32;  sattn[li * WIN + lane + 32] = (j >= 0 && j < N_UTT) ? e1 * inv : 0.f;
        j = i + lane - WHALF + 64;  sattn[li * WIN + lane + 64] = (j >= 0 && j < N_UTT) ? e2 * inv : 0.f;
        j = i + lane - WHALF + 96;  sattn[li * WIN + lane + 96] = (j >= 0 && j < N_UTT) ? e3 * inv : 0.f;
    }
    __syncthreads();

    // ---- coefficient tables [jj][li=16] ----
    float* const csAp = reinterpret_cast<float*>(sm + OFF_CSAP);
    float* const csAs = reinterpret_cast<float*>(sm + OFF_CSAS);
    float* const csB  = reinterpret_cast<float*>(sm + OFF_CSB);
    for (int t = tid; t < NW * G; t += 256) {
        const int jj = t >> 4, li = t & 15;
        const int w = jj - li;
        const float c = (w >= 0 && w < WIN) ? sattn[li * WIN + w] : 0.f;
        csAp[t] = (w >= WHALF) ? c : 0.f;
        csAs[t] = (w < WHALF) ? c : 0.f;
        csB[t]  = (spkw[jj] == spkw[WHALF + li]) ? 0.5f * c : -0.5f * c;
    }
    __syncthreads();

    // ---- aggregation ----
    const int d = tid;
    float acc[G];
#pragma unroll
    for (int li = 0; li < G; li++) acc[li] = 0.f;

    const int jlo = (i0 < WHALF) ? (WHALF - i0) : 0;
    const int jhi = min(NW, N_UTT - i0 + WHALF);

#define AGGH(AV, BV, HB, T1V, T2V)                                                   \
    do {                                                                             \
        const float4 a0 = *reinterpret_cast<const float4*>(&(AV)[jj * 16 + (HB)]);   \
        const float4 a1 = *reinterpret_cast<const float4*>(&(AV)[jj * 16 + (HB) + 4]);\
        const float4 b0 = *reinterpret_cast<const float4*>(&(BV)[jj * 16 + (HB)]);   \
        const float4 b1 = *reinterpret_cast<const float4*>(&(BV)[jj * 16 + (HB) + 4]);\
        acc[(HB) + 0] = fmaf(a0.x, (T1V), fmaf(b0.x, (T2V), acc[(HB) + 0]));         \
        acc[(HB) + 1] = fmaf(a0.y, (T1V), fmaf(b0.y, (T2V), acc[(HB) + 1]));         \
        acc[(HB) + 2] = fmaf(a0.z, (T1V), fmaf(b0.z, (T2V), acc[(HB) + 2]));         \
        acc[(HB) + 3] = fmaf(a0.w, (T1V), fmaf(b0.w, (T2V), acc[(HB) + 3]));         \
        acc[(HB) + 4] = fmaf(a1.x, (T1V), fmaf(b1.x, (T2V), acc[(HB) + 4]));         \
        acc[(HB) + 5] = fmaf(a1.y, (T1V), fmaf(b1.y, (T2V), acc[(HB) + 5]));         \
        acc[(HB) + 6] = fmaf(a1.z, (T1V), fmaf(b1.z, (T2V), acc[(HB) + 6]));         \
        acc[(HB) + 7] = fmaf(a1.w, (T1V), fmaf(b1.w, (T2V), acc[(HB) + 7]));         \
    } while (0)

#pragma unroll 4
    for (int jj = jlo; jj < WHALF; jj++) {
        const size_t off = (size_t)(i0 + jj - WHALF) * DIM + d;
        const float t1 = T1s[off], t2 = T2[off];
        AGGH(csAs, csB, 0, t1, t2);
        AGGH(csAs, csB, 8, t1, t2);
    }
    for (int jj = WHALF; jj < WHALF + G - 1; jj++) {
        const size_t off = (size_t)(i0 + jj - WHALF) * DIM + d;
        const float t1p = T1p[off], t1s = T1s[off], t2 = T2[off];
#pragma unroll
        for (int hb = 0; hb < 16; hb += 8) {
            const float4 p0 = *reinterpret_cast<const float4*>(&csAp[jj * 16 + hb]);
            const float4 p1 = *reinterpret_cast<const float4*>(&csAp[jj * 16 + hb + 4]);
            const float4 s0 = *reinterpret_cast<const float4*>(&csAs[jj * 16 + hb]);
            const float4 s1 = *reinterpret_cast<const float4*>(&csAs[jj * 16 + hb + 4]);
            const float4 b0 = *reinterpret_cast<const float4*>(&csB[jj * 16 + hb]);
            const float4 b1 = *reinterpret_cast<const float4*>(&csB[jj * 16 + hb + 4]);
            acc[hb + 0] = fmaf(p0.x, t1p, fmaf(s0.x, t1s, fmaf(b0.x, t2, acc[hb + 0])));
            acc[hb + 1] = fmaf(p0.y, t1p, fmaf(s0.y, t1s, fmaf(b0.y, t2, acc[hb + 1])));
            acc[hb + 2] = fmaf(p0.z, t1p, fmaf(s0.z, t1s, fmaf(b0.z, t2, acc[hb + 2])));
            acc[hb + 3] = fmaf(p0.w, t1p, fmaf(s0.w, t1s, fmaf(b0.w, t2, acc[hb + 3])));
            acc[hb + 4] = fmaf(p1.x, t1p, fmaf(s1.x, t1s, fmaf(b1.x, t2, acc[hb + 4])));
            acc[hb + 5] = fmaf(p1.y, t1p, fmaf(s1.y, t1s, fmaf(b1.y, t2, acc[hb + 5])));
            acc[hb + 6] = fmaf(p1.z, t1p, fmaf(s1.z, t1s, fmaf(b1.z, t2, acc[hb + 6])));
            acc[hb + 7] = fmaf(p1.w, t1p, fmaf(s1.w, t1s, fmaf(b1.w, t2, acc[hb + 7])));
        }
    }
#pragma unroll 4
    for (int jj = WHALF + G - 1; jj < jhi; jj++) {
        const size_t off = (size_t)(i0 + jj - WHALF) * DIM + d;
        const float t1 = T1p[off], t2 = T2[off];
        AGGH(csAp, csB, 0, t1, t2);
        AGGH(csAp, csB, 8, t1, t2);
    }

    // ---- log_softmax over D ----
    float* const s_acc = reinterpret_cast<float*>(sm + OFF_SACC);
    __syncthreads();
#pragma unroll
    for (int li = 0; li < G; li++) s_acc[li * DIM + d] = acc[li];
    __syncthreads();
#pragma unroll
    for (int rr = 0; rr < 2; rr++) {
        const int r = wi + rr * 8;
        float v[8];
#pragma unroll
        for (int k = 0; k < 8; k++) v[k] = s_acc[r * DIM + lane + 32 * k];
        float m = v[0];
#pragma unroll
        for (int k = 1; k < 8; k++) m = fmaxf(m, v[k]);
        m = warpMax(m);
        float s = 0.f;
#pragma unroll
        for (int k = 0; k < 8; k++) s += __expf(v[k] - m);
        s = warpSum(s);
        if (lane == 0) slse[r] = m + logf(s);
    }
    __syncthreads();
#pragma unroll
    for (int li = 0; li < G; li++)
        out[(size_t)(i0 + li) * DIM + d] = acc[li] - slse[li];
}

// ---------------------------------------------------------------------------
extern "C" void kernel_launch(void* const* d_in, const int* in_sizes, int n_in,
                              void* d_out, int out_size) {
    const float* x   = (const float*)d_in[0];
    const int*   spk = (const int*)d_in[1];
    const float* Wa  = (const float*)d_in[2];
    const float* Wp  = (const float*)d_in[3];
    const float* Ws  = (const float*)d_in[4];
    const float* Wm  = (const float*)d_in[5];
    const float* Wd  = (const float*)d_in[6];
    float* out = (float*)d_out;

    cudaFuncSetAttribute(gemm_tc_kernel, cudaFuncAttributeMaxDynamicSharedMemorySize, GSM_TOTAL);
    cudaFuncSetAttribute(fused_kernel, cudaFuncAttributeMaxDynamicSharedMemorySize, SMF_TOTAL);

    prep_w_kernel<<<DIM * DIM / 256, 256>>>(Wa, Wp, Ws, Wm, Wd);
    gemm_tc_kernel<<<dim3(N_UTT / 128, 8), 256, GSM_TOTAL>>>(x);
    fused_kernel<<<N_UTT / G, 256, SMF_TOTAL>>>(x, spk, out);
}